// round 10
// baseline (speedup 1.0000x reference)
#include <cuda_runtime.h>
#include <mma.h>
#include <stdint.h>
#include <math.h>

using namespace nvcuda;

#define IC 1024
#define OC 512
#define HH 64
#define WWW 64
#define NB 2
#define NA 16384
#define PRE_NMS_K 6000
#define POST_NMS_K 300

// ---- wmma conv params ----
#define NITER 288                 // K stages of 32 (9 taps x 32 ic-chunks)
#define TILE_B 55296              // 3 splits x 128 rows x 144B
#define STAGE_B (2 * TILE_B)      // A + B = 110592
#define B_OFF2 TILE_B
#define CONV_SMEM (2 * STAGE_B)   // 221184

// ---- ffma2 fallback conv params (round-3 validated) ----
#define ICC 8
#define OCT 32
#define HT 4
#define IPITCH 68
#define WNUM (ICC*9*OCT)
#define INUM (ICC*6*IPITCH)
#define NCHUNK (IC/ICC)
#define NOCT (OC/OCT)

// ---------------- scratch (static device allocations, allowed) ----------------
__device__ float g_x[NB * OC * HH * WWW];
__device__ float g_wA[4 * NITER * 3 * 4096];     // [mt][i][s][m*32+k] plain layout
__device__ float g_xs3[NB * 66 * 66 * 3 * 1024]; // [b][pr][pc][s][ic]
__device__ float g_wr[NCHUNK * NOCT * WNUM];
__device__ float g_ipad[NB * IC * 66 * IPITCH];
__device__ float g_scores[NB * NA];
__device__ float4 g_boxes[NB * NA];
__device__ int   g_flag;

__device__ __forceinline__ unsigned ordkey(float f) {
    unsigned u = __float_as_uint(f);
    return (u & 0x80000000u) ? ~u : (u | 0x80000000u);
}
#define ORD_NEG_INF 0x007FFFFFu

__device__ __forceinline__ float to_tf32(float v) {
    float r;
    asm("cvt.rna.tf32.f32 %0, %1;" : "=f"(r) : "f"(v));
    return r;
}

// ---- packed f32x2 helpers (fallback conv) ----
__device__ __forceinline__ unsigned long long bc2(float f) {
    unsigned long long r; unsigned u = __float_as_uint(f);
    asm("mov.b64 %0, {%1, %1};" : "=l"(r) : "r"(u));
    return r;
}
#define FMA2(d, a, b, c) \
    asm("fma.rn.f32x2 %0, %1, %2, %3;" : "=l"(d) : "l"(a), "l"(b), "l"(c))
__device__ __forceinline__ float lo32(unsigned long long v) {
    return __uint_as_float((unsigned)v);
}
__device__ __forceinline__ float hi32(unsigned long long v) {
    return __uint_as_float((unsigned)(v >> 32));
}

__global__ void zero_flag_kernel() { g_flag = 0; }

// ============ Pre-pass A: weights -> plain [mt][i][s][m][k32] tf32 splits =====
__global__ __launch_bounds__(256) void prep_w_wmma(const float* __restrict__ Wc)
{
    int idx = blockIdx.x * 256 + threadIdx.x;
    if (idx >= 4 * NITER * 4096) return;
    int k   = idx & 31;
    int m   = (idx >> 5) & 127;
    int blk = idx >> 12;            // mt*288 + i
    int i   = blk % NITER;
    int mt  = blk / NITER;
    int oc  = mt * 128 + m;
    int t   = i >> 5;
    int ic  = (i & 31) * 32 + k;
    float v  = Wc[((size_t)oc * IC + ic) * 9 + t];
    float a0 = to_tf32(v);
    float r1 = v - a0;
    float a1 = to_tf32(r1);
    float a2 = to_tf32(r1 - a1);
    size_t base = (size_t)blk * 12288 + m * 32 + k;
    g_wA[base]        = a0;
    g_wA[base + 4096] = a1;
    g_wA[base + 8192] = a2;
}

// ============ Pre-pass B: input -> padded [b][pr][pc][s][ic] tf32 splits ======
__global__ __launch_bounds__(256) void prep_x_tc(const float* __restrict__ in)
{
    int idx = blockIdx.x * 256 + threadIdx.x;
    if (idx >= NB * 66 * 66 * 1024) return;
    int ic = idx & 1023;
    int pix = idx >> 10;
    int pc = pix % 66;
    int rest2 = pix / 66;
    int pr = rest2 % 66;
    int b  = rest2 / 66;
    int h = pr - 1, w = pc - 1;
    float v = 0.f;
    if (h >= 0 && h < HH && w >= 0 && w < WWW)
        v = in[(((size_t)b * IC + ic) * HH + h) * WWW + w];
    float a0 = to_tf32(v);
    float r1 = v - a0;
    float a1 = to_tf32(r1);
    float a2 = to_tf32(r1 - a1);
    size_t base = (size_t)pix * 3072 + ic;
    g_xs3[base]        = a0;
    g_xs3[base + 1024] = a1;
    g_xs3[base + 2048] = a2;
}

// ============= Kernel 1: implicit-GEMM conv via wmma tf32 x3 ==================
// grid (4 mt, 32 nt, 2 b), 256 threads (8 warps), 1 block/SM.
// Block: D[128 oc][128 px]; warp tile 64(m) x 32(n) via m16n16k8 frags.
// Compiler-owned fragment layouts (load/store_matrix_sync) — no hand maps.
__global__ __launch_bounds__(256) void conv_wmma_kernel(const float* __restrict__ bc)
{
    extern __shared__ char smem[];
    const int tid  = threadIdx.x;
    const int wid  = tid >> 5;
    const int mt = blockIdx.x;
    const int nt = blockIdx.y;
    const int b  = blockIdx.z;
    const int h0 = nt * 2;
    const int wm = wid & 1;        // m half (64 oc)
    const int wn = wid >> 1;       // n quarter (32 px)

    wmma::fragment<wmma::accumulator, 16, 16, 8, float> c[4][2];
#pragma unroll
    for (int mf = 0; mf < 4; mf++)
#pragma unroll
        for (int nf = 0; nf < 2; nf++)
            wmma::fill_fragment(c[mf][nf], 0.f);

    const char*  asrc0 = (const char*)(g_wA + (size_t)mt * NITER * 12288);
    const float* xb    = g_xs3 + (size_t)b * 66 * 66 * 3072;

    int bl_n[12], bl_u[12], bl_s[12];
#pragma unroll
    for (int j = 0; j < 12; j++) {
        int id = tid + j * 256;
        bl_s[j] = id >> 10;
        bl_n[j] = (id >> 3) & 127;
        bl_u[j] = id & 7;
    }

    auto issue = [&](int i, int st) {
        char* sa = smem + st * STAGE_B;
        unsigned au = (unsigned)__cvta_generic_to_shared(sa);
        const char* asrc = asrc0 + (size_t)i * 49152;
        // A: contiguous global -> pitch-144 rows [s*128+m][u]
#pragma unroll
        for (int j = 0; j < 12; j++) {
            int id = tid + j * 256;
            unsigned dst = au + (unsigned)((id >> 3) * 144 + (id & 7) * 16);
            asm volatile("cp.async.cg.shared.global [%0], [%1], 16;"
                         :: "r"(dst), "l"(asrc + id * 16));
        }
        int t = i >> 5, c32 = i & 31;
        int kh = t / 3, kw = t - kh * 3;
        unsigned bu = au + B_OFF2;
#pragma unroll
        for (int j = 0; j < 12; j++) {
            int n = bl_n[j];
            int pr = h0 + (n >> 6) + kh;
            int pc = (n & 63) + kw;
            const float* src = xb + (size_t)(pr * 66 + pc) * 3072 + (bl_s[j] << 10)
                                  + (c32 << 5) + (bl_u[j] << 2);
            unsigned dst = bu + bl_s[j] * 18432 + n * 144 + bl_u[j] * 16;
            asm volatile("cp.async.cg.shared.global [%0], [%1], 16;"
                         :: "r"(dst), "l"(src));
        }
        asm volatile("cp.async.commit_group;");
    };

    issue(0, 0);

    for (int i = 0; i < NITER; i++) {
        const int st = i & 1;
        if (i + 1 < NITER) {
            issue(i + 1, st ^ 1);
            asm volatile("cp.async.wait_group 1;");
        } else {
            asm volatile("cp.async.wait_group 0;");
        }
        __syncthreads();

        const float* A_ = (const float*)(smem + st * STAGE_B);
        const float* B_ = (const float*)(smem + st * STAGE_B + B_OFF2);

#pragma unroll
        for (int kk8 = 0; kk8 < 4; kk8++) {
            wmma::fragment<wmma::matrix_a, 16, 16, 8,
                           wmma::precision::tf32, wmma::row_major> a[3][4];
            wmma::fragment<wmma::matrix_b, 16, 16, 8,
                           wmma::precision::tf32, wmma::col_major> bf[3][2];
#pragma unroll
            for (int s = 0; s < 3; s++)
#pragma unroll
                for (int mf = 0; mf < 4; mf++)
                    wmma::load_matrix_sync(a[s][mf],
                        A_ + s * 4608 + (wm * 64 + mf * 16) * 36 + kk8 * 8, 36);
#pragma unroll
            for (int s = 0; s < 3; s++)
#pragma unroll
                for (int nf = 0; nf < 2; nf++)
                    wmma::load_matrix_sync(bf[s][nf],
                        B_ + s * 4608 + (wn * 32 + nf * 16) * 36 + kk8 * 8, 36);
#pragma unroll
            for (int mf = 0; mf < 4; mf++)
#pragma unroll
                for (int nf = 0; nf < 2; nf++) {
                    wmma::mma_sync(c[mf][nf], a[0][mf], bf[0][nf], c[mf][nf]);
                    wmma::mma_sync(c[mf][nf], a[0][mf], bf[1][nf], c[mf][nf]);
                    wmma::mma_sync(c[mf][nf], a[1][mf], bf[0][nf], c[mf][nf]);
                    wmma::mma_sync(c[mf][nf], a[1][mf], bf[1][nf], c[mf][nf]);
                    wmma::mma_sync(c[mf][nf], a[0][mf], bf[2][nf], c[mf][nf]);
                    wmma::mma_sync(c[mf][nf], a[2][mf], bf[0][nf], c[mf][nf]);
                }
        }
        __syncthreads();
    }

    // ---- epilogue: C frags -> smem (pitch 132) -> bias+relu -> g_x ----
    float* csm = (float*)smem;
#pragma unroll
    for (int mf = 0; mf < 4; mf++)
#pragma unroll
        for (int nf = 0; nf < 2; nf++)
            wmma::store_matrix_sync(
                csm + (wm * 64 + mf * 16) * 132 + wn * 32 + nf * 16,
                c[mf][nf], 132, wmma::mem_row_major);
    __syncthreads();

    {
        const int m    = tid >> 1;
        const int half = tid & 1;
        const int oc   = mt * 128 + m;
        const float bias = bc[oc];
        const int h = h0 + half;
        float* op = g_x + ((size_t)(b * OC + oc) * HH + h) * WWW;
        const float* cr = csm + m * 132 + half * 64;
#pragma unroll
        for (int q = 0; q < 16; q++) {
            float4 v = *(const float4*)(cr + q * 4);
            v.x = fmaxf(v.x + bias, 0.f);
            v.y = fmaxf(v.y + bias, 0.f);
            v.z = fmaxf(v.z + bias, 0.f);
            v.w = fmaxf(v.w + bias, 0.f);
            *(float4*)(op + q * 4) = v;
        }
    }
}

// ============ check kernel: sampled direct fp32 conv vs g_x ===================
__global__ __launch_bounds__(128) void check_kernel(
    const float* __restrict__ in, const float* __restrict__ Wc,
    const float* __restrict__ bc)
{
    __shared__ float part[128];
    const int oc = blockIdx.x, b = blockIdx.y, tid = threadIdx.x;
    const int p = tid & 15, slice = tid >> 4;
    const int hs[4] = {0, 1, 31, 63};
    const int ws[4] = {0, 1, 32, 63};
    const int h = hs[p >> 2], w = ws[p & 3];

    float s = 0.f;
    const float* wrow0 = Wc + (size_t)oc * IC * 9;
    for (int ic = slice * 128; ic < slice * 128 + 128; ic++) {
        const float* wrow = wrow0 + (size_t)ic * 9;
        const float* irow = in + ((size_t)(b * IC + ic) * HH) * WWW;
#pragma unroll
        for (int kh = 0; kh < 3; kh++) {
            int ih = h - 1 + kh;
            if (ih < 0 || ih >= HH) continue;
#pragma unroll
            for (int kw = 0; kw < 3; kw++) {
                int iw = w - 1 + kw;
                if (iw < 0 || iw >= WWW) continue;
                s += wrow[kh * 3 + kw] * irow[ih * WWW + iw];
            }
        }
    }
    part[tid] = s;
    __syncthreads();
    if (tid < 16) {
        float tot = 0.f;
        for (int sl = 0; sl < 8; sl++) tot += part[sl * 16 + tid];
        float v = fmaxf(tot + bc[oc], 0.f);
        float ref = g_x[(((size_t)(b * OC + oc) * HH) + h) * WWW + w];
        float rel = fabsf(v - ref) / fmaxf(fabsf(v), 1.0f);
        if (rel > 1e-4f) atomicOr(&g_flag, 1);
    }
}

// ================= fallback path (round-3 validated, gated) ===================
__global__ __launch_bounds__(256) void prep_weights(const float* __restrict__ Wc)
{
    if (g_flag == 0) return;
    int idx = blockIdx.x * 256 + threadIdx.x;
    if (idx >= NCHUNK * NOCT * WNUM) return;
    int c  = idx / (NOCT * WNUM);
    int r  = idx - c * (NOCT * WNUM);
    int ot = r / WNUM;
    int e  = r - ot * WNUM;
    int icl = e / 288;
    int e2  = e - icl * 288;
    int k   = e2 >> 5;
    int ocl = e2 & 31;
    g_wr[idx] = Wc[((size_t)(ot * 32 + ocl) * IC + c * ICC + icl) * 9 + k];
}

__global__ __launch_bounds__(256) void prep_input(const float* __restrict__ in)
{
    if (g_flag == 0) return;
    int idx = blockIdx.x * 256 + threadIdx.x;
    const int TOT = NB * IC * 66 * IPITCH;
    if (idx >= TOT) return;
    int bi  = idx / (66 * IPITCH);
    int r   = idx - bi * (66 * IPITCH);
    int row = r / IPITCH;
    int col = r - row * IPITCH;
    int h   = row - 1;
    int w   = col - 1;
    float v = 0.f;
    if (h >= 0 && h < HH && w >= 0 && w < WWW && col < 66)
        v = in[((size_t)bi * HH + h) * WWW + w];
    g_ipad[idx] = v;
}

__global__ __launch_bounds__(128, 3) void conv_ffma2_kernel(const float* __restrict__ bc)
{
    if (g_flag == 0) return;
    __shared__ float sW[2][WNUM];
    __shared__ float sIn[2][INUM];

    const int oc0 = blockIdx.x * OCT;
    const int h0  = blockIdx.y * HT;
    const int b   = blockIdx.z;
    const int tid = threadIdx.x;

    const int tz  = tid >> 5;
    const int to0 = ((tid >> 3) & 3) * 8;
    const int tw0 = (tid & 7) * 8;

    const unsigned sW_u[2] = {
        (unsigned)__cvta_generic_to_shared(&sW[0][0]),
        (unsigned)__cvta_generic_to_shared(&sW[1][0]) };
    const unsigned sIn_u[2] = {
        (unsigned)__cvta_generic_to_shared(&sIn[0][0]),
        (unsigned)__cvta_generic_to_shared(&sIn[1][0]) };

    const float* wbase = g_wr + (size_t)blockIdx.x * WNUM;
    int i_icl[7], i_off[7];
#pragma unroll
    for (int s = 0; s < 7; s++) {
        int idx4 = tid + s * 128;
        int icl  = idx4 / 102;
        int r    = idx4 - icl * 102;
        int row  = r / 17;
        int c4   = r - row * 17;
        i_icl[s] = icl;
        i_off[s] = (h0 + row) * IPITCH + c4 * 4;
    }

    unsigned long long acc2[4][8];
#pragma unroll
    for (int p = 0; p < 4; p++)
#pragma unroll
        for (int j = 0; j < 8; j++) acc2[p][j] = 0ull;

    auto issue_chunk = [&](int kc, int bu) {
        const unsigned sWu  = sW_u[bu];
        const unsigned sInu = sIn_u[bu];
        const float* ws = wbase + (size_t)kc * (NOCT * WNUM);
#pragma unroll
        for (int s = 0; s < 5; s++) {
            int idx4 = tid + s * 128;
            if (idx4 < WNUM / 4) {
                const float* g = ws + idx4 * 4;
                asm volatile("cp.async.cg.shared.global [%0], [%1], 16;"
                             :: "r"(sWu + (unsigned)(idx4 * 16)), "l"(g));
            }
        }
        const int ic0 = kc * ICC;
#pragma unroll
        for (int s = 0; s < 7; s++) {
            int idx4 = tid + s * 128;
            if (idx4 < INUM / 4) {
                const float* g = g_ipad +
                    ((size_t)(b * IC + ic0 + i_icl[s]) * 66) * IPITCH + i_off[s];
                asm volatile("cp.async.cg.shared.global [%0], [%1], 16;"
                             :: "r"(sInu + (unsigned)(idx4 * 16)), "l"(g));
            }
        }
        asm volatile("cp.async.commit_group;");
    };

    issue_chunk(0, 0);

    for (int kc = 0; kc < NCHUNK; kc++) {
        const int cur = kc & 1;
        if (kc < NCHUNK - 1) {
            issue_chunk(kc + 1, cur ^ 1);
            asm volatile("cp.async.wait_group 1;");
        } else {
            asm volatile("cp.async.wait_group 0;");
        }
        __syncthreads();

        const float* W_ = sW[cur];
        const float* I_ = sIn[cur];

#pragma unroll 1
        for (int ic = 0; ic < ICC; ic++) {
            const float* irow = I_ + (ic * 6 + tz) * IPITCH + tw0;
            const float* wrow = W_ + ic * 9 * OCT + to0;
#pragma unroll
            for (int kh = 0; kh < 3; kh++) {
                float4 f0 = *(const float4*)(irow + kh * IPITCH);
                float4 f1 = *(const float4*)(irow + kh * IPITCH + 4);
                float4 f2 = *(const float4*)(irow + kh * IPITCH + 8);
                unsigned long long ib[10];
                ib[0] = bc2(f0.x); ib[1] = bc2(f0.y); ib[2] = bc2(f0.z); ib[3] = bc2(f0.w);
                ib[4] = bc2(f1.x); ib[5] = bc2(f1.y); ib[6] = bc2(f1.z); ib[7] = bc2(f1.w);
                ib[8] = bc2(f2.x); ib[9] = bc2(f2.y);
#pragma unroll
                for (int kw = 0; kw < 3; kw++) {
                    const ulonglong2* wp =
                        (const ulonglong2*)(wrow + (kh * 3 + kw) * OCT);
                    ulonglong2 wa = wp[0];
                    ulonglong2 wb = wp[1];
#pragma unroll
                    for (int j = 0; j < 8; j++) {
                        FMA2(acc2[0][j], wa.x, ib[j + kw], acc2[0][j]);
                        FMA2(acc2[1][j], wa.y, ib[j + kw], acc2[1][j]);
                        FMA2(acc2[2][j], wb.x, ib[j + kw], acc2[2][j]);
                        FMA2(acc2[3][j], wb.y, ib[j + kw], acc2[3][j]);
                    }
                }
            }
        }
        __syncthreads();
    }

    const int h = h0 + tz;
#pragma unroll
    for (int p = 0; p < 4; p++) {
#pragma unroll
        for (int s = 0; s < 2; s++) {
            int oc = oc0 + to0 + 2 * p + s;
            float bias = bc[oc];
            float* op = &g_x[((size_t)(b * OC + oc) * HH + h) * WWW + tw0];
#pragma unroll
            for (int j = 0; j < 8; j++) {
                float v = (s == 0 ? lo32(acc2[p][j]) : hi32(acc2[p][j])) + bias;
                op[j] = v > 0.f ? v : 0.f;
            }
        }
    }
}

// ============ Kernel 2: heads (round-3 validated 64-thread version) ===========
__global__ __launch_bounds__(64) void heads_kernel(
    const float* __restrict__ meta,
    const float* __restrict__ Wcls, const float* __restrict__ bcls,
    const float* __restrict__ Wbb,  const float* __restrict__ bbb)
{
    __shared__ float sw[512 * 20];
    __shared__ float sb[20];

    const int h = blockIdx.x, b = blockIdx.y, tid = threadIdx.x;

    for (int idx = tid; idx < 512 * 20; idx += 64) {
        int c = idx / 20, o = idx - c * 20;
        sw[idx] = (o < 4) ? Wcls[o * 512 + c] : Wbb[(o - 4) * 512 + c];
    }
    if (tid < 20) sb[tid] = (tid < 4) ? bcls[tid] : bbb[tid - 4];
    __syncthreads();

    const int w = tid;
    float acc[20];
#pragma unroll
    for (int o = 0; o < 20; o++) acc[o] = 0.f;

    const float* xp = g_x + ((size_t)(b * OC) * HH + h) * WWW + w;
    for (int c = 0; c < 512; c++) {
        float xv = xp[(size_t)c * HH * WWW];
        const float4* wp = reinterpret_cast<const float4*>(&sw[c * 20]);
        float4 w0 = wp[0], w1 = wp[1], w2 = wp[2], w3 = wp[3], w4 = wp[4];
        acc[0]  = fmaf(xv, w0.x, acc[0]);  acc[1]  = fmaf(xv, w0.y, acc[1]);
        acc[2]  = fmaf(xv, w0.z, acc[2]);  acc[3]  = fmaf(xv, w0.w, acc[3]);
        acc[4]  = fmaf(xv, w1.x, acc[4]);  acc[5]  = fmaf(xv, w1.y, acc[5]);
        acc[6]  = fmaf(xv, w1.z, acc[6]);  acc[7]  = fmaf(xv, w1.w, acc[7]);
        acc[8]  = fmaf(xv, w2.x, acc[8]);  acc[9]  = fmaf(xv, w2.y, acc[9]);
        acc[10] = fmaf(xv, w2.z, acc[10]); acc[11] = fmaf(xv, w2.w, acc[11]);
        acc[12] = fmaf(xv, w3.x, acc[12]); acc[13] = fmaf(xv, w3.y, acc[13]);
        acc[14] = fmaf(xv, w3.z, acc[14]); acc[15] = fmaf(xv, w3.w, acc[15]);
        acc[16] = fmaf(xv, w4.x, acc[16]); acc[17] = fmaf(xv, w4.y, acc[17]);
        acc[18] = fmaf(xv, w4.z, acc[18]); acc[19] = fmaf(xv, w4.w, acc[19]);
    }

    float s[4];
#pragma unroll
    for (int a = 0; a < 4; a++) s[a] = acc[a] + sb[a];
    float prob[4];
#pragma unroll
    for (int a = 0; a < 4; a++) {
        int p = a ^ 2;
        float m  = fmaxf(s[a], s[p]);
        float ea = expf(s[a] - m);
        float eb = expf(s[p] - m);
        prob[a]  = ea / (ea + eb);
    }

    const float im_h = meta[b * 3 + 0];
    const float im_w = meta[b * 3 + 1];
    const float scl  = meta[b * 3 + 2];
    const float minsz = 16.f * scl;

    const int base = b * NA + (h * 64 + w) * 4;
#pragma unroll
    for (int a = 0; a < 4; a++) {
        float wa = (float)(64 << a);
        float cx = w * 16.f + 8.f;
        float cy = h * 16.f + 8.f;
        float d0 = acc[4 + a * 4 + 0] + sb[4 + a * 4 + 0];
        float d1 = acc[4 + a * 4 + 1] + sb[4 + a * 4 + 1];
        float d2 = acc[4 + a * 4 + 2] + sb[4 + a * 4 + 2];
        float d3 = acc[4 + a * 4 + 3] + sb[4 + a * 4 + 3];
        float pcx = d0 * wa + cx, pcy = d1 * wa + cy;
        float pw  = expf(d2) * wa, ph = expf(d3) * wa;
        float x1 = pcx - 0.5f * pw, y1 = pcy - 0.5f * ph;
        float x2 = pcx + 0.5f * pw, y2 = pcy + 0.5f * ph;
        x1 = fminf(fmaxf(x1, 0.f), im_w - 1.f);
        x2 = fminf(fmaxf(x2, 0.f), im_w - 1.f);
        y1 = fminf(fmaxf(y1, 0.f), im_h - 1.f);
        y2 = fminf(fmaxf(y2, 0.f), im_h - 1.f);
        bool keep = (x2 - x1 + 1.f >= minsz) && (y2 - y1 + 1.f >= minsz);
        g_scores[base + a] = keep ? prob[a] : -INFINITY;
        g_boxes[base + a]  = make_float4(x1, y1, x2, y2);
    }
}

// ================= Kernel 3: exact top-6000 mark (per image) ==================
__global__ __launch_bounds__(1024) void topk_kernel()
{
    const int b   = blockIdx.x;
    const int tid = threadIdx.x;
    float* scores = g_scores + b * NA;

    unsigned key[16];
    const int i0 = tid * 16;
#pragma unroll
    for (int i = 0; i < 16; i++) key[i] = ordkey(scores[i0 + i]);

    __shared__ int wsum[32];
    __shared__ int s_total;
    const int lane = tid & 31, wid = tid >> 5;

    auto count_ge = [&](unsigned cand) -> int {
        int local = 0;
#pragma unroll
        for (int i = 0; i < 16; i++) local += (key[i] >= cand) ? 1 : 0;
        for (int off = 16; off; off >>= 1)
            local += __shfl_down_sync(0xFFFFFFFFu, local, off);
        if (lane == 0) wsum[wid] = local;
        __syncthreads();
        if (tid == 0) {
            int st = 0;
            for (int k = 0; k < 32; k++) st += wsum[k];
            s_total = st;
        }
        __syncthreads();
        int r = s_total;
        __syncthreads();
        return r;
    };

    unsigned thr = 0;
    for (int bit = 31; bit >= 0; bit--) {
        unsigned cand = thr | (1u << bit);
        if (count_ge(cand) >= PRE_NMS_K) thr = cand;
    }
    const int n_gt = count_ge(thr + 1u);
    const int need = PRE_NMS_K - n_gt;

    int my_eq = 0;
#pragma unroll
    for (int i = 0; i < 16; i++) my_eq += (key[i] == thr) ? 1 : 0;

    int v = my_eq;
    for (int off = 1; off < 32; off <<= 1) {
        int tt = __shfl_up_sync(0xFFFFFFFFu, v, off);
        if (lane >= off) v += tt;
    }
    __syncthreads();
    if (lane == 31) wsum[wid] = v;
    __syncthreads();
    if (wid == 0) {
        int sv = wsum[lane];
        for (int off = 1; off < 32; off <<= 1) {
            int tt = __shfl_up_sync(0xFFFFFFFFu, sv, off);
            if (lane >= off) sv += tt;
        }
        wsum[lane] = sv;
    }
    __syncthreads();
    int rank = v - my_eq + (wid ? wsum[wid - 1] : 0);

#pragma unroll
    for (int i = 0; i < 16; i++) {
        if (key[i] == thr) {
            if (rank >= need) scores[i0 + i] = -INFINITY;
            rank++;
        } else if (key[i] < thr) {
            scores[i0 + i] = -INFINITY;
        }
    }
}

// ===================== Kernel 4: exact greedy NMS (per image) =================
__global__ __launch_bounds__(512) void nms_kernel(float* __restrict__ out)
{
    const int b   = blockIdx.x;
    const int tid = threadIdx.x;
    const float4* boxes = g_boxes + b * NA;

    float sc[32];
    const int i0 = tid * 32;
#pragma unroll
    for (int i = 0; i < 32; i++) sc[i] = g_scores[b * NA + i0 + i];

    __shared__ unsigned long long swm[16];
    __shared__ unsigned long long s_best;
    __shared__ float4 s_box;
    __shared__ float  s_area;
    __shared__ int    s_firstj;

    const int lane = tid & 31, wid = tid >> 5;

    for (int it = 0; it < POST_NMS_K; it++) {
        unsigned long long loc = ((unsigned long long)ORD_NEG_INF << 32);
#pragma unroll
        for (int i = 0; i < 32; i++) {
            unsigned long long kk =
                ((unsigned long long)ordkey(sc[i]) << 32) |
                (unsigned)(65535 - (i0 + i));
            loc = (kk > loc) ? kk : loc;
        }
        for (int off = 16; off; off >>= 1) {
            unsigned long long o = __shfl_down_sync(0xFFFFFFFFu, loc, off);
            loc = (o > loc) ? o : loc;
        }
        if (lane == 0) swm[wid] = loc;
        __syncthreads();
        if (tid < 16) {
            unsigned long long vv = swm[tid];
            for (int off = 8; off; off >>= 1) {
                unsigned long long o = __shfl_down_sync(0x0000FFFFu, vv, off);
                vv = (o > vv) ? o : vv;
            }
            if (tid == 0) s_best = vv;
        }
        __syncthreads();

        if (tid == 0) {
            unsigned long long best = s_best;
            unsigned keypart = (unsigned)(best >> 32);
            int j;
            if (keypart == ORD_NEG_INF && it > 0) j = s_firstj;
            else j = 65535 - (int)(best & 0xFFFFFFFFull);
            if (it == 0) s_firstj = j;
            float4 bx = boxes[j];
            s_box  = bx;
            s_area = (bx.z - bx.x + 1.f) * (bx.w - bx.y + 1.f);
            float* o = out + (size_t)(b * POST_NMS_K + it) * 5;
            o[0] = (float)b; o[1] = bx.x; o[2] = bx.y; o[3] = bx.z; o[4] = bx.w;
        }
        __syncthreads();

        const float4 jb = s_box;
        const float  ja = s_area;
#pragma unroll 4
        for (int i = 0; i < 32; i++) {
            float4 bb = boxes[i0 + i];
            float xx1 = fmaxf(jb.x, bb.x);
            float yy1 = fmaxf(jb.y, bb.y);
            float xx2 = fminf(jb.z, bb.z);
            float yy2 = fminf(jb.w, bb.w);
            float iw  = fmaxf(xx2 - xx1 + 1.f, 0.f);
            float ih  = fmaxf(yy2 - yy1 + 1.f, 0.f);
            float inter = iw * ih;
            float area  = (bb.z - bb.x + 1.f) * (bb.w - bb.y + 1.f);
            float iou   = inter / (ja + area - inter);
            if (iou > 0.7f) sc[i] = -INFINITY;
        }
    }
}

// ================================ launcher ====================================
extern "C" void kernel_launch(void* const* d_in, const int* in_sizes, int n_in,
                              void* d_out, int out_size)
{
    const float* feat = (const float*)d_in[0];
    const float* meta = (const float*)d_in[1];
    const float* Wc   = (const float*)d_in[3];
    const float* bc   = (const float*)d_in[4];
    const float* Wcls = (const float*)d_in[5];
    const float* bcls = (const float*)d_in[6];
    const float* Wbb  = (const float*)d_in[7];
    const float* bbb  = (const float*)d_in[8];
    float* out = (float*)d_out;

    cudaFuncSetAttribute(conv_wmma_kernel,
                         cudaFuncAttributeMaxDynamicSharedMemorySize, CONV_SMEM);

    zero_flag_kernel<<<1, 1>>>();
    // --- wmma path (compiler-owned fragment layouts) ---
    prep_w_wmma<<<(4 * NITER * 4096 + 255) / 256, 256>>>(Wc);
    prep_x_tc<<<(NB * 66 * 66 * 1024 + 255) / 256, 256>>>(feat);
    conv_wmma_kernel<<<dim3(4, 32, 2), 256, CONV_SMEM>>>(bc);
    // --- verify samples; set g_flag if wmma conv is wrong ---
    check_kernel<<<dim3(512, 2), 128>>>(feat, Wc, bc);
    // --- validated fallback path (runs only if flag set) ---
    prep_weights<<<(NCHUNK * NOCT * WNUM + 255) / 256, 256>>>(Wc);
    prep_input<<<(NB * IC * 66 * IPITCH + 255) / 256, 256>>>(feat);
    conv_ffma2_kernel<<<dim3(16, 16, 2), 128>>>(bc);
    // --- validated tail ---
    heads_kernel<<<dim3(64, 2), 64>>>(meta, Wcls, bcls, Wbb, bbb);
    topk_kernel<<<2, 1024>>>();
    nms_kernel<<<2, 512>>>(out);
}

// round 12
// speedup vs baseline: 1.4093x; 1.4093x over previous
#include <cuda_runtime.h>
#include <stdint.h>
#include <math.h>

#define IC 1024
#define OC 512
#define HH 64
#define WWW 64
#define NB 2
#define NA 16384
#define PRE_NMS_K 6000
#define POST_NMS_K 300

// ---- mma conv params ----
#define NKK8 1152                 // K/8 = 9216/8 (tap-major: t*1024+ic)
#define NITER 288                 // K stages of 32 (9 taps x 32 ic-chunks)
#define STAGE_BYTES 104448        // A 49152 + B 55296
#define B_OFF 49152
#define CONV_SMEM (2 * STAGE_BYTES)   // 208896

// ---- ffma2 fallback conv params (round-3 validated) ----
#define ICC 8
#define OCT 32
#define HT 4
#define IPITCH 68
#define WNUM (ICC*9*OCT)
#define INUM (ICC*6*IPITCH)
#define NCHUNK (IC/ICC)
#define NOCT (OC/OCT)

// ---------------- scratch (static device allocations, allowed) ----------------
__device__ float g_x[NB * OC * HH * WWW];
__device__ float g_wtc[4 * NKK8 * 3 * 8 * 32 * 4];
__device__ float g_xs3[NB * 66 * 66 * 3 * 1024];
__device__ float g_wr[NCHUNK * NOCT * WNUM];
__device__ float g_ipad[NB * IC * 66 * IPITCH];
__device__ float g_scores[NB * NA];
__device__ float4 g_boxes[NB * NA];
__device__ int   g_flag;

__device__ __forceinline__ unsigned ordkey(float f) {
    unsigned u = __float_as_uint(f);
    return (u & 0x80000000u) ? ~u : (u | 0x80000000u);
}
#define ORD_NEG_INF 0x007FFFFFu

// tf32 split by explicit mantissa truncation (does NOT rely on cvt.rna.tf32
// actually truncating — round 6/7/11 evidence says it may be a no-op mov):
// keep top 10 mantissa bits; term passes through HW tf32 truncation exactly.
__device__ __forceinline__ float tf32_trunc(float v) {
    return __uint_as_float(__float_as_uint(v) & 0xFFFFE000u);
}

#define MMA_TF32(c, a, b) \
    asm volatile("mma.sync.aligned.m16n8k8.row.col.f32.tf32.tf32.f32 " \
        "{%0,%1,%2,%3}, {%4,%5,%6,%7}, {%8,%9}, {%0,%1,%2,%3};" \
        : "+f"((c)[0]), "+f"((c)[1]), "+f"((c)[2]), "+f"((c)[3]) \
        : "r"((a).x), "r"((a).y), "r"((a).z), "r"((a).w), \
          "r"((b)[0]), "r"((b)[1]))

// ---- packed f32x2 helpers (fallback conv) ----
__device__ __forceinline__ unsigned long long bc2(float f) {
    unsigned long long r; unsigned u = __float_as_uint(f);
    asm("mov.b64 %0, {%1, %1};" : "=l"(r) : "r"(u));
    return r;
}
#define FMA2(d, a, b, c) \
    asm("fma.rn.f32x2 %0, %1, %2, %3;" : "=l"(d) : "l"(a), "l"(b), "l"(c))
__device__ __forceinline__ float lo32(unsigned long long v) {
    return __uint_as_float((unsigned)v);
}
__device__ __forceinline__ float hi32(unsigned long long v) {
    return __uint_as_float((unsigned)(v >> 32));
}

__global__ void zero_flag_kernel() { g_flag = 0; }

// ======================= mma path pre-passes ==================================
// A-fragment per PTX ISA m16n8k8.tf32:
//   r0:(m,k) r1:(m+8,k) r2:(m,k+4) r3:(m+8,k+4); m=lam>>2, k=lam&3
// v = a0 + a1 + a2 EXACTLY (each term <=10 mantissa bits).
__global__ __launch_bounds__(256) void prep_w_tc(const float* __restrict__ Wc)
{
    int idx = blockIdx.x * 256 + threadIdx.x;
    if (idx >= 4 * NKK8 * 8 * 32 * 4) return;
    int r   = idx & 3;
    int lam = (idx >> 2) & 31;
    int mf  = (idx >> 7) & 7;
    int rest = idx >> 10;
    int kk8 = rest % NKK8;
    int mt  = rest / NKK8;
    int oc = mt * 128 + mf * 16 + (lam >> 2) + (r & 1) * 8;
    int t  = kk8 / 128;
    int ic = (kk8 % 128) * 8 + (lam & 3) + (r >> 1) * 4;
    float v  = Wc[((size_t)oc * IC + ic) * 9 + t];
    float a0 = tf32_trunc(v);
    float r1 = v - a0;
    float a1 = tf32_trunc(r1);
    float a2 = r1 - a1;
    size_t base = (size_t)(mt * NKK8 + kk8) * 3072 + mf * 128 + lam * 4 + r;
    g_wtc[base]        = a0;
    g_wtc[base + 1024] = a1;
    g_wtc[base + 2048] = a2;
}

__global__ __launch_bounds__(256) void prep_x_tc(const float* __restrict__ in)
{
    int idx = blockIdx.x * 256 + threadIdx.x;
    if (idx >= NB * 66 * 66 * 1024) return;
    int ic = idx & 1023;
    int pix = idx >> 10;
    int pc = pix % 66;
    int rest2 = pix / 66;
    int pr = rest2 % 66;
    int b  = rest2 / 66;
    int h = pr - 1, w = pc - 1;
    float v = 0.f;
    if (h >= 0 && h < HH && w >= 0 && w < WWW)
        v = in[(((size_t)b * IC + ic) * HH + h) * WWW + w];
    float a0 = tf32_trunc(v);
    float r1 = v - a0;
    float a1 = tf32_trunc(r1);
    float a2 = r1 - a1;
    size_t base = (size_t)pix * 3072 + ic;
    g_xs3[base]        = a0;
    g_xs3[base + 1024] = a1;
    g_xs3[base + 2048] = a2;
}

// ====================== mma conv (round-7 structure, masked splits) ===========
__global__ __launch_bounds__(256, 1) void conv_mma_kernel(const float* __restrict__ bc)
{
    extern __shared__ char smem[];
    const int tid  = threadIdx.x;
    const int wid  = tid >> 5;
    const int lane = tid & 31;
    const int mt = blockIdx.x;
    const int nt = blockIdx.y;
    const int b  = blockIdx.z;
    const int h0 = nt * 2;
    const int wm = wid & 1;
    const int wn = wid >> 1;

    float acc[4][4][4];
#pragma unroll
    for (int i = 0; i < 4; i++)
#pragma unroll
        for (int j = 0; j < 4; j++)
#pragma unroll
            for (int r = 0; r < 4; r++) acc[i][j][r] = 0.f;

    const char*  wsrc = (const char*)(g_wtc + (size_t)mt * NKK8 * 3072);
    const float* xb   = g_xs3 + (size_t)b * 66 * 66 * 3072;

    int bl_n[12], bl_u[12], bl_s[12];
#pragma unroll
    for (int j = 0; j < 12; j++) {
        int id = tid + j * 256;
        bl_s[j] = id >> 10;              // split 0..2
        bl_n[j] = (id >> 3) & 127;       // pixel 0..127
        bl_u[j] = id & 7;                // 4-float group within 32 k
    }

    auto issue = [&](int i, int st) {
        char* sa = smem + st * STAGE_BYTES;
        const char* asrc = wsrc + (size_t)i * 49152;
        unsigned au = (unsigned)__cvta_generic_to_shared(sa);
#pragma unroll
        for (int j = 0; j < 12; j++) {
            int off = (tid + j * 256) * 16;
            asm volatile("cp.async.cg.shared.global [%0], [%1], 16;"
                         :: "r"(au + off), "l"(asrc + off));
        }
        int t = i >> 5, c32 = i & 31;
        int kh = t / 3, kw = t - kh * 3;
        unsigned bu = au + B_OFF;
#pragma unroll
        for (int j = 0; j < 12; j++) {
            int n = bl_n[j];
            int pr = h0 + (n >> 6) + kh;
            int pc = (n & 63) + kw;
            const float* src = xb + (size_t)(pr * 66 + pc) * 3072 + (bl_s[j] << 10)
                                  + (c32 << 5) + (bl_u[j] << 2);
            unsigned dst = bu + bl_s[j] * 18432 + n * 144 + bl_u[j] * 16;
            asm volatile("cp.async.cg.shared.global [%0], [%1], 16;"
                         :: "r"(dst), "l"(src));
        }
        asm volatile("cp.async.commit_group;");
    };

    issue(0, 0);

    for (int i = 0; i < NITER; i++) {
        const int st = i & 1;
        if (i + 1 < NITER) {
            issue(i + 1, st ^ 1);
            asm volatile("cp.async.wait_group 1;");
        } else {
            asm volatile("cp.async.wait_group 0;");
        }
        __syncthreads();

        const char* sa = smem + st * STAGE_BYTES;
#pragma unroll
        for (int kk8 = 0; kk8 < 4; kk8++) {
            uint4 a[3][4];
#pragma unroll
            for (int s = 0; s < 3; s++)
#pragma unroll
                for (int mf = 0; mf < 4; mf++)
                    a[s][mf] = *(const uint4*)(sa +
                        (((kk8 * 3 + s) * 8 + (wm * 4 + mf)) * 512) + lane * 16);
            uint32_t bb[3][4][2];
#pragma unroll
            for (int s = 0; s < 3; s++)
#pragma unroll
                for (int nf = 0; nf < 4; nf++) {
                    const char* ba = sa + B_OFF + s * 18432
                        + (wn * 32 + nf * 8 + (lane >> 2)) * 144
                        + (kk8 * 8 + (lane & 3)) * 4;
                    bb[s][nf][0] = *(const uint32_t*)ba;
                    bb[s][nf][1] = *(const uint32_t*)(ba + 16);
                }
#pragma unroll
            for (int mf = 0; mf < 4; mf++)
#pragma unroll
                for (int nf = 0; nf < 4; nf++) {
                    MMA_TF32(acc[mf][nf], a[0][mf], bb[0][nf]);
                    MMA_TF32(acc[mf][nf], a[0][mf], bb[1][nf]);
                    MMA_TF32(acc[mf][nf], a[1][mf], bb[0][nf]);
                    MMA_TF32(acc[mf][nf], a[1][mf], bb[1][nf]);
                    MMA_TF32(acc[mf][nf], a[0][mf], bb[2][nf]);
                    MMA_TF32(acc[mf][nf], a[2][mf], bb[0][nf]);
                }
        }
        __syncthreads();
    }

#pragma unroll
    for (int mf = 0; mf < 4; mf++) {
        int oc0 = mt * 128 + wm * 64 + mf * 16 + (lane >> 2);
        float bias0 = bc[oc0];
        float bias8 = bc[oc0 + 8];
#pragma unroll
        for (int nf = 0; nf < 4; nf++) {
            int nl = wn * 32 + nf * 8 + (lane & 3) * 2;
            int h = h0 + (nl >> 6);
            int w = nl & 63;
            float2 v0, v1;
            v0.x = fmaxf(acc[mf][nf][0] + bias0, 0.f);
            v0.y = fmaxf(acc[mf][nf][1] + bias0, 0.f);
            v1.x = fmaxf(acc[mf][nf][2] + bias8, 0.f);
            v1.y = fmaxf(acc[mf][nf][3] + bias8, 0.f);
            *(float2*)(g_x + (((size_t)(b * OC + oc0) * HH + h) * WWW + w))     = v0;
            *(float2*)(g_x + (((size_t)(b * OC + oc0 + 8) * HH + h) * WWW + w)) = v1;
        }
    }
}

// ============ check kernel: sampled direct fp32 conv vs g_x ===================
// Correct split -> errors ~5e-6 abs; pure-tf32 failure mode ~1.5e-4. Threshold 5e-5.
__global__ __launch_bounds__(128) void check_kernel(
    const float* __restrict__ in, const float* __restrict__ Wc,
    const float* __restrict__ bc)
{
    __shared__ float part[128];
    const int oc = blockIdx.x, b = blockIdx.y, tid = threadIdx.x;
    const int p = tid & 15, slice = tid >> 4;
    const int hs[4] = {0, 1, 31, 63};
    const int ws[4] = {0, 1, 32, 63};
    const int h = hs[p >> 2], w = ws[p & 3];

    float s = 0.f;
    const float* wrow0 = Wc + (size_t)oc * IC * 9;
    for (int ic = slice * 128; ic < slice * 128 + 128; ic++) {
        const float* wrow = wrow0 + (size_t)ic * 9;
        const float* irow = in + ((size_t)(b * IC + ic) * HH) * WWW;
#pragma unroll
        for (int kh = 0; kh < 3; kh++) {
            int ih = h - 1 + kh;
            if (ih < 0 || ih >= HH) continue;
#pragma unroll
            for (int kw = 0; kw < 3; kw++) {
                int iw = w - 1 + kw;
                if (iw < 0 || iw >= WWW) continue;
                s += wrow[kh * 3 + kw] * irow[ih * WWW + iw];
            }
        }
    }
    part[tid] = s;
    __syncthreads();
    if (tid < 16) {
        float tot = 0.f;
        for (int sl = 0; sl < 8; sl++) tot += part[sl * 16 + tid];
        float v = fmaxf(tot + bc[oc], 0.f);
        float ref = g_x[(((size_t)(b * OC + oc) * HH) + h) * WWW + w];
        float rel = fabsf(v - ref) / fmaxf(fabsf(v), 1.0f);
        if (rel > 5e-5f) atomicOr(&g_flag, 1);
    }
}

// ================= fallback path (round-3 validated, gated) ===================
__global__ __launch_bounds__(256) void prep_weights(const float* __restrict__ Wc)
{
    if (g_flag == 0) return;
    int idx = blockIdx.x * 256 + threadIdx.x;
    if (idx >= NCHUNK * NOCT * WNUM) return;
    int c  = idx / (NOCT * WNUM);
    int r  = idx - c * (NOCT * WNUM);
    int ot = r / WNUM;
    int e  = r - ot * WNUM;
    int icl = e / 288;
    int e2  = e - icl * 288;
    int k   = e2 >> 5;
    int ocl = e2 & 31;
    g_wr[idx] = Wc[((size_t)(ot * 32 + ocl) * IC + c * ICC + icl) * 9 + k];
}

__global__ __launch_bounds__(256) void prep_input(const float* __restrict__ in)
{
    if (g_flag == 0) return;
    int idx = blockIdx.x * 256 + threadIdx.x;
    const int TOT = NB * IC * 66 * IPITCH;
    if (idx >= TOT) return;
    int bi  = idx / (66 * IPITCH);
    int r   = idx - bi * (66 * IPITCH);
    int row = r / IPITCH;
    int col = r - row * IPITCH;
    int h   = row - 1;
    int w   = col - 1;
    float v = 0.f;
    if (h >= 0 && h < HH && w >= 0 && w < WWW && col < 66)
        v = in[((size_t)bi * HH + h) * WWW + w];
    g_ipad[idx] = v;
}

__global__ __launch_bounds__(128, 3) void conv_ffma2_kernel(const float* __restrict__ bc)
{
    if (g_flag == 0) return;
    __shared__ float sW[2][WNUM];
    __shared__ float sIn[2][INUM];

    const int oc0 = blockIdx.x * OCT;
    const int h0  = blockIdx.y * HT;
    const int b   = blockIdx.z;
    const int tid = threadIdx.x;

    const int tz  = tid >> 5;
    const int to0 = ((tid >> 3) & 3) * 8;
    const int tw0 = (tid & 7) * 8;

    const unsigned sW_u[2] = {
        (unsigned)__cvta_generic_to_shared(&sW[0][0]),
        (unsigned)__cvta_generic_to_shared(&sW[1][0]) };
    const unsigned sIn_u[2] = {
        (unsigned)__cvta_generic_to_shared(&sIn[0][0]),
        (unsigned)__cvta_generic_to_shared(&sIn[1][0]) };

    const float* wbase = g_wr + (size_t)blockIdx.x * WNUM;
    int i_icl[7], i_off[7];
#pragma unroll
    for (int s = 0; s < 7; s++) {
        int idx4 = tid + s * 128;
        int icl  = idx4 / 102;
        int r    = idx4 - icl * 102;
        int row  = r / 17;
        int c4   = r - row * 17;
        i_icl[s] = icl;
        i_off[s] = (h0 + row) * IPITCH + c4 * 4;
    }

    unsigned long long acc2[4][8];
#pragma unroll
    for (int p = 0; p < 4; p++)
#pragma unroll
        for (int j = 0; j < 8; j++) acc2[p][j] = 0ull;

    auto issue_chunk = [&](int kc, int bu) {
        const unsigned sWu  = sW_u[bu];
        const unsigned sInu = sIn_u[bu];
        const float* ws = wbase + (size_t)kc * (NOCT * WNUM);
#pragma unroll
        for (int s = 0; s < 5; s++) {
            int idx4 = tid + s * 128;
            if (idx4 < WNUM / 4) {
                const float* g = ws + idx4 * 4;
                asm volatile("cp.async.cg.shared.global [%0], [%1], 16;"
                             :: "r"(sWu + (unsigned)(idx4 * 16)), "l"(g));
            }
        }
        const int ic0 = kc * ICC;
#pragma unroll
        for (int s = 0; s < 7; s++) {
            int idx4 = tid + s * 128;
            if (idx4 < INUM / 4) {
                const float* g = g_ipad +
                    ((size_t)(b * IC + ic0 + i_icl[s]) * 66) * IPITCH + i_off[s];
                asm volatile("cp.async.cg.shared.global [%0], [%1], 16;"
                             :: "r"(sInu + (unsigned)(idx4 * 16)), "l"(g));
            }
        }
        asm volatile("cp.async.commit_group;");
    };

    issue_chunk(0, 0);

    for (int kc = 0; kc < NCHUNK; kc++) {
        const int cur = kc & 1;
        if (kc < NCHUNK - 1) {
            issue_chunk(kc + 1, cur ^ 1);
            asm volatile("cp.async.wait_group 1;");
        } else {
            asm volatile("cp.async.wait_group 0;");
        }
        __syncthreads();

        const float* W_ = sW[cur];
        const float* I_ = sIn[cur];

#pragma unroll 1
        for (int ic = 0; ic < ICC; ic++) {
            const float* irow = I_ + (ic * 6 + tz) * IPITCH + tw0;
            const float* wrow = W_ + ic * 9 * OCT + to0;
#pragma unroll
            for (int kh = 0; kh < 3; kh++) {
                float4 f0 = *(const float4*)(irow + kh * IPITCH);
                float4 f1 = *(const float4*)(irow + kh * IPITCH + 4);
                float4 f2 = *(const float4*)(irow + kh * IPITCH + 8);
                unsigned long long ib[10];
                ib[0] = bc2(f0.x); ib[1] = bc2(f0.y); ib[2] = bc2(f0.z); ib[3] = bc2(f0.w);
                ib[4] = bc2(f1.x); ib[5] = bc2(f1.y); ib[6] = bc2(f1.z); ib[7] = bc2(f1.w);
                ib[8] = bc2(f2.x); ib[9] = bc2(f2.y);
#pragma unroll
                for (int kw = 0; kw < 3; kw++) {
                    const ulonglong2* wp =
                        (const ulonglong2*)(wrow + (kh * 3 + kw) * OCT);
                    ulonglong2 wa = wp[0];
                    ulonglong2 wb = wp[1];
#pragma unroll
                    for (int j = 0; j < 8; j++) {
                        FMA2(acc2[0][j], wa.x, ib[j + kw], acc2[0][j]);
                        FMA2(acc2[1][j], wa.y, ib[j + kw], acc2[1][j]);
                        FMA2(acc2[2][j], wb.x, ib[j + kw], acc2[2][j]);
                        FMA2(acc2[3][j], wb.y, ib[j + kw], acc2[3][j]);
                    }
                }
            }
        }
        __syncthreads();
    }

    const int h = h0 + tz;
#pragma unroll
    for (int p = 0; p < 4; p++) {
#pragma unroll
        for (int s = 0; s < 2; s++) {
            int oc = oc0 + to0 + 2 * p + s;
            float bias = bc[oc];
            float* op = &g_x[((size_t)(b * OC + oc) * HH + h) * WWW + tw0];
#pragma unroll
            for (int j = 0; j < 8; j++) {
                float v = (s == 0 ? lo32(acc2[p][j]) : hi32(acc2[p][j])) + bias;
                op[j] = v > 0.f ? v : 0.f;
            }
        }
    }
}

// ============ Kernel 2: heads (round-3 validated 64-thread version) ===========
__global__ __launch_bounds__(64) void heads_kernel(
    const float* __restrict__ meta,
    const float* __restrict__ Wcls, const float* __restrict__ bcls,
    const float* __restrict__ Wbb,  const float* __restrict__ bbb)
{
    __shared__ float sw[512 * 20];
    __shared__ float sb[20];

    const int h = blockIdx.x, b = blockIdx.y, tid = threadIdx.x;

    for (int idx = tid; idx < 512 * 20; idx += 64) {
        int c = idx / 20, o = idx - c * 20;
        sw[idx] = (o < 4) ? Wcls[o * 512 + c] : Wbb[(o - 4) * 512 + c];
    }
    if (tid < 20) sb[tid] = (tid < 4) ? bcls[tid] : bbb[tid - 4];
    __syncthreads();

    const int w = tid;
    float acc[20];
#pragma unroll
    for (int o = 0; o < 20; o++) acc[o] = 0.f;

    const float* xp = g_x + ((size_t)(b * OC) * HH + h) * WWW + w;
    for (int c = 0; c < 512; c++) {
        float xv = xp[(size_t)c * HH * WWW];
        const float4* wp = reinterpret_cast<const float4*>(&sw[c * 20]);
        float4 w0 = wp[0], w1 = wp[1], w2 = wp[2], w3 = wp[3], w4 = wp[4];
        acc[0]  = fmaf(xv, w0.x, acc[0]);  acc[1]  = fmaf(xv, w0.y, acc[1]);
        acc[2]  = fmaf(xv, w0.z, acc[2]);  acc[3]  = fmaf(xv, w0.w, acc[3]);
        acc[4]  = fmaf(xv, w1.x, acc[4]);  acc[5]  = fmaf(xv, w1.y, acc[5]);
        acc[6]  = fmaf(xv, w1.z, acc[6]);  acc[7]  = fmaf(xv, w1.w, acc[7]);
        acc[8]  = fmaf(xv, w2.x, acc[8]);  acc[9]  = fmaf(xv, w2.y, acc[9]);
        acc[10] = fmaf(xv, w2.z, acc[10]); acc[11] = fmaf(xv, w2.w, acc[11]);
        acc[12] = fmaf(xv, w3.x, acc[12]); acc[13] = fmaf(xv, w3.y, acc[13]);
        acc[14] = fmaf(xv, w3.z, acc[14]); acc[15] = fmaf(xv, w3.w, acc[15]);
        acc[16] = fmaf(xv, w4.x, acc[16]); acc[17] = fmaf(xv, w4.y, acc[17]);
        acc[18] = fmaf(xv, w4.z, acc[18]); acc[19] = fmaf(xv, w4.w, acc[19]);
    }

    float s[4];
#pragma unroll
    for (int a = 0; a < 4; a++) s[a] = acc[a] + sb[a];
    float prob[4];
#pragma unroll
    for (int a = 0; a < 4; a++) {
        int p = a ^ 2;
        float m  = fmaxf(s[a], s[p]);
        float ea = expf(s[a] - m);
        float eb = expf(s[p] - m);
        prob[a]  = ea / (ea + eb);
    }

    const float im_h = meta[b * 3 + 0];
    const float im_w = meta[b * 3 + 1];
    const float scl  = meta[b * 3 + 2];
    const float minsz = 16.f * scl;

    const int base = b * NA + (h * 64 + w) * 4;
#pragma unroll
    for (int a = 0; a < 4; a++) {
        float wa = (float)(64 << a);
        float cx = w * 16.f + 8.f;
        float cy = h * 16.f + 8.f;
        float d0 = acc[4 + a * 4 + 0] + sb[4 + a * 4 + 0];
        float d1 = acc[4 + a * 4 + 1] + sb[4 + a * 4 + 1];
        float d2 = acc[4 + a * 4 + 2] + sb[4 + a * 4 + 2];
        float d3 = acc[4 + a * 4 + 3] + sb[4 + a * 4 + 3];
        float pcx = d0 * wa + cx, pcy = d1 * wa + cy;
        float pw  = expf(d2) * wa, ph = expf(d3) * wa;
        float x1 = pcx - 0.5f * pw, y1 = pcy - 0.5f * ph;
        float x2 = pcx + 0.5f * pw, y2 = pcy + 0.5f * ph;
        x1 = fminf(fmaxf(x1, 0.f), im_w - 1.f);
        x2 = fminf(fmaxf(x2, 0.f), im_w - 1.f);
        y1 = fminf(fmaxf(y1, 0.f), im_h - 1.f);
        y2 = fminf(fmaxf(y2, 0.f), im_h - 1.f);
        bool keep = (x2 - x1 + 1.f >= minsz) && (y2 - y1 + 1.f >= minsz);
        g_scores[base + a] = keep ? prob[a] : -INFINITY;
        g_boxes[base + a]  = make_float4(x1, y1, x2, y2);
    }
}

// ================= Kernel 3: exact top-6000 mark (per image) ==================
__global__ __launch_bounds__(1024) void topk_kernel()
{
    const int b   = blockIdx.x;
    const int tid = threadIdx.x;
    float* scores = g_scores + b * NA;

    unsigned key[16];
    const int i0 = tid * 16;
#pragma unroll
    for (int i = 0; i < 16; i++) key[i] = ordkey(scores[i0 + i]);

    __shared__ int wsum[32];
    __shared__ int s_total;
    const int lane = tid & 31, wid = tid >> 5;

    auto count_ge = [&](unsigned cand) -> int {
        int local = 0;
#pragma unroll
        for (int i = 0; i < 16; i++) local += (key[i] >= cand) ? 1 : 0;
        for (int off = 16; off; off >>= 1)
            local += __shfl_down_sync(0xFFFFFFFFu, local, off);
        if (lane == 0) wsum[wid] = local;
        __syncthreads();
        if (tid == 0) {
            int st = 0;
            for (int k = 0; k < 32; k++) st += wsum[k];
            s_total = st;
        }
        __syncthreads();
        int r = s_total;
        __syncthreads();
        return r;
    };

    unsigned thr = 0;
    for (int bit = 31; bit >= 0; bit--) {
        unsigned cand = thr | (1u << bit);
        if (count_ge(cand) >= PRE_NMS_K) thr = cand;
    }
    const int n_gt = count_ge(thr + 1u);
    const int need = PRE_NMS_K - n_gt;

    int my_eq = 0;
#pragma unroll
    for (int i = 0; i < 16; i++) my_eq += (key[i] == thr) ? 1 : 0;

    int v = my_eq;
    for (int off = 1; off < 32; off <<= 1) {
        int tt = __shfl_up_sync(0xFFFFFFFFu, v, off);
        if (lane >= off) v += tt;
    }
    __syncthreads();
    if (lane == 31) wsum[wid] = v;
    __syncthreads();
    if (wid == 0) {
        int sv = wsum[lane];
        for (int off = 1; off < 32; off <<= 1) {
            int tt = __shfl_up_sync(0xFFFFFFFFu, sv, off);
            if (lane >= off) sv += tt;
        }
        wsum[lane] = sv;
    }
    __syncthreads();
    int rank = v - my_eq + (wid ? wsum[wid - 1] : 0);

#pragma unroll
    for (int i = 0; i < 16; i++) {
        if (key[i] == thr) {
            if (rank >= need) scores[i0 + i] = -INFINITY;
            rank++;
        } else if (key[i] < thr) {
            scores[i0 + i] = -INFINITY;
        }
    }
}

// ===================== Kernel 4: exact greedy NMS (per image) =================
__global__ __launch_bounds__(512) void nms_kernel(float* __restrict__ out)
{
    const int b   = blockIdx.x;
    const int tid = threadIdx.x;
    const float4* boxes = g_boxes + b * NA;

    float sc[32];
    const int i0 = tid * 32;
#pragma unroll
    for (int i = 0; i < 32; i++) sc[i] = g_scores[b * NA + i0 + i];

    __shared__ unsigned long long swm[16];
    __shared__ unsigned long long s_best;
    __shared__ float4 s_box;
    __shared__ float  s_area;
    __shared__ int    s_firstj;

    const int lane = tid & 31, wid = tid >> 5;

    for (int it = 0; it < POST_NMS_K; it++) {
        unsigned long long loc = ((unsigned long long)ORD_NEG_INF << 32);
#pragma unroll
        for (int i = 0; i < 32; i++) {
            unsigned long long kk =
                ((unsigned long long)ordkey(sc[i]) << 32) |
                (unsigned)(65535 - (i0 + i));
            loc = (kk > loc) ? kk : loc;
        }
        for (int off = 16; off; off >>= 1) {
            unsigned long long o = __shfl_down_sync(0xFFFFFFFFu, loc, off);
            loc = (o > loc) ? o : loc;
        }
        if (lane == 0) swm[wid] = loc;
        __syncthreads();
        if (tid < 16) {
            unsigned long long vv = swm[tid];
            for (int off = 8; off; off >>= 1) {
                unsigned long long o = __shfl_down_sync(0x0000FFFFu, vv, off);
                vv = (o > vv) ? o : vv;
            }
            if (tid == 0) s_best = vv;
        }
        __syncthreads();

        if (tid == 0) {
            unsigned long long best = s_best;
            unsigned keypart = (unsigned)(best >> 32);
            int j;
            if (keypart == ORD_NEG_INF && it > 0) j = s_firstj;
            else j = 65535 - (int)(best & 0xFFFFFFFFull);
            if (it == 0) s_firstj = j;
            float4 bx = boxes[j];
            s_box  = bx;
            s_area = (bx.z - bx.x + 1.f) * (bx.w - bx.y + 1.f);
            float* o = out + (size_t)(b * POST_NMS_K + it) * 5;
            o[0] = (float)b; o[1] = bx.x; o[2] = bx.y; o[3] = bx.z; o[4] = bx.w;
        }
        __syncthreads();

        const float4 jb = s_box;
        const float  ja = s_area;
#pragma unroll 4
        for (int i = 0; i < 32; i++) {
            float4 bb = boxes[i0 + i];
            float xx1 = fmaxf(jb.x, bb.x);
            float yy1 = fmaxf(jb.y, bb.y);
            float xx2 = fminf(jb.z, bb.z);
            float yy2 = fminf(jb.w, bb.w);
            float iw  = fmaxf(xx2 - xx1 + 1.f, 0.f);
            float ih  = fmaxf(yy2 - yy1 + 1.f, 0.f);
            float inter = iw * ih;
            float area  = (bb.z - bb.x + 1.f) * (bb.w - bb.y + 1.f);
            float iou   = inter / (ja + area - inter);
            if (iou > 0.7f) sc[i] = -INFINITY;
        }
    }
}

// ================================ launcher ====================================
extern "C" void kernel_launch(void* const* d_in, const int* in_sizes, int n_in,
                              void* d_out, int out_size)
{
    const float* feat = (const float*)d_in[0];
    const float* meta = (const float*)d_in[1];
    const float* Wc   = (const float*)d_in[3];
    const float* bc   = (const float*)d_in[4];
    const float* Wcls = (const float*)d_in[5];
    const float* bcls = (const float*)d_in[6];
    const float* Wbb  = (const float*)d_in[7];
    const float* bbb  = (const float*)d_in[8];
    float* out = (float*)d_out;

    cudaFuncSetAttribute(conv_mma_kernel,
                         cudaFuncAttributeMaxDynamicSharedMemorySize, CONV_SMEM);

    zero_flag_kernel<<<1, 1>>>();
    // --- mma path: bit-masked tf32 3-splits (exact decomposition) ---
    prep_w_tc<<<(4 * NKK8 * 1024 + 255) / 256, 256>>>(Wc);
    prep_x_tc<<<(NB * 66 * 66 * 1024 + 255) / 256, 256>>>(feat);
    conv_mma_kernel<<<dim3(4, 32, 2), 256, CONV_SMEM>>>(bc);
    // --- verify samples; set g_flag if mma conv is wrong ---
    check_kernel<<<dim3(512, 2), 128>>>(feat, Wc, bc);
    // --- validated fallback path (runs only if flag set) ---
    prep_weights<<<(NCHUNK * NOCT * WNUM + 255) / 256, 256>>>(Wc);
    prep_input<<<(NB * IC * 66 * IPITCH + 255) / 256, 256>>>(feat);
    conv_ffma2_kernel<<<dim3(16, 16, 2), 128>>>(bc);
    // --- validated tail (64-thread heads) ---
    heads_kernel<<<dim3(64, 2), 64>>>(meta, Wcls, bcls, Wbb, bbb);
    topk_kernel<<<2, 1024>>>();
    nms_kernel<<<2, 512>>>(out);
}

// round 13
// speedup vs baseline: 1.4104x; 1.0008x over previous
#include <cuda_runtime.h>
#include <stdint.h>
#include <math.h>

#define IC 1024
#define OC 512
#define HH 64
#define WWW 64
#define NB 2
#define NA 16384
#define PRE_NMS_K 6000
#define POST_NMS_K 300

// ---- mma conv params ----
#define NKK8 1152                 // K/8 = 9216/8 (tap-major: t*1024+ic)
#define NITER 288                 // K stages of 32 (9 taps x 32 ic-chunks)
#define STAGE_BYTES 104448        // A 49152 + B 55296
#define B_OFF 49152
#define CONV_SMEM (2 * STAGE_BYTES)   // 208896

// ---- ffma2 fallback conv params (round-3 validated) ----
#define ICC 8
#define OCT 32
#define HT 4
#define IPITCH 68
#define WNUM (ICC*9*OCT)
#define INUM (ICC*6*IPITCH)
#define NCHUNK (IC/ICC)
#define NOCT (OC/OCT)

// ---------------- scratch (static device allocations, allowed) ----------------
__device__ float g_x[NB * OC * HH * WWW];
__device__ float g_wtc[4 * NKK8 * 3 * 8 * 32 * 4];
__device__ float g_xs3[NB * 66 * 66 * 3 * 1024];
__device__ float g_wr[NCHUNK * NOCT * WNUM];
__device__ float g_ipad[NB * IC * 66 * IPITCH];
__device__ float g_scores[NB * NA];
__device__ float4 g_boxes[NB * NA];
__device__ int   g_flag;

__device__ __forceinline__ unsigned ordkey(float f) {
    unsigned u = __float_as_uint(f);
    return (u & 0x80000000u) ? ~u : (u | 0x80000000u);
}
#define ORD_NEG_INF 0x007FFFFFu

// ROUND-13: 8-significand-bit chunks (bf16-exact). Three chunks decompose the
// fp32 significand EXACTLY, and each chunk survives any HW input truncation
// >= 8 bits (robust to both honest-tf32 and bf16-class mma hardware).
__device__ __forceinline__ float chunk8(float v) {
    return __uint_as_float(__float_as_uint(v) & 0xFFFF0000u);
}

#define MMA_TF32(c, a, b) \
    asm volatile("mma.sync.aligned.m16n8k8.row.col.f32.tf32.tf32.f32 " \
        "{%0,%1,%2,%3}, {%4,%5,%6,%7}, {%8,%9}, {%0,%1,%2,%3};" \
        : "+f"((c)[0]), "+f"((c)[1]), "+f"((c)[2]), "+f"((c)[3]) \
        : "r"((a).x), "r"((a).y), "r"((a).z), "r"((a).w), \
          "r"((b)[0]), "r"((b)[1]))

// ---- packed f32x2 helpers (fallback conv) ----
__device__ __forceinline__ unsigned long long bc2(float f) {
    unsigned long long r; unsigned u = __float_as_uint(f);
    asm("mov.b64 %0, {%1, %1};" : "=l"(r) : "r"(u));
    return r;
}
#define FMA2(d, a, b, c) \
    asm("fma.rn.f32x2 %0, %1, %2, %3;" : "=l"(d) : "l"(a), "l"(b), "l"(c))
__device__ __forceinline__ float lo32(unsigned long long v) {
    return __uint_as_float((unsigned)v);
}
__device__ __forceinline__ float hi32(unsigned long long v) {
    return __uint_as_float((unsigned)(v >> 32));
}

__global__ void zero_flag_kernel() { g_flag = 0; }

// ======================= mma path pre-passes ==================================
// A-fragment per PTX ISA m16n8k8.tf32:
//   r0:(m,k) r1:(m+8,k) r2:(m,k+4) r3:(m+8,k+4); m=lam>>2, k=lam&3
// v = c0 + c1 + c2 EXACTLY (each chunk has <=8 significand bits).
__global__ __launch_bounds__(256) void prep_w_tc(const float* __restrict__ Wc)
{
    int idx = blockIdx.x * 256 + threadIdx.x;
    if (idx >= 4 * NKK8 * 8 * 32 * 4) return;
    int r   = idx & 3;
    int lam = (idx >> 2) & 31;
    int mf  = (idx >> 7) & 7;
    int rest = idx >> 10;
    int kk8 = rest % NKK8;
    int mt  = rest / NKK8;
    int oc = mt * 128 + mf * 16 + (lam >> 2) + (r & 1) * 8;
    int t  = kk8 / 128;
    int ic = (kk8 % 128) * 8 + (lam & 3) + (r >> 1) * 4;
    float v  = Wc[((size_t)oc * IC + ic) * 9 + t];
    float a0 = chunk8(v);
    float r1 = v - a0;
    float a1 = chunk8(r1);
    float a2 = r1 - a1;
    size_t base = (size_t)(mt * NKK8 + kk8) * 3072 + mf * 128 + lam * 4 + r;
    g_wtc[base]        = a0;
    g_wtc[base + 1024] = a1;
    g_wtc[base + 2048] = a2;
}

__global__ __launch_bounds__(256) void prep_x_tc(const float* __restrict__ in)
{
    int idx = blockIdx.x * 256 + threadIdx.x;
    if (idx >= NB * 66 * 66 * 1024) return;
    int ic = idx & 1023;
    int pix = idx >> 10;
    int pc = pix % 66;
    int rest2 = pix / 66;
    int pr = rest2 % 66;
    int b  = rest2 / 66;
    int h = pr - 1, w = pc - 1;
    float v = 0.f;
    if (h >= 0 && h < HH && w >= 0 && w < WWW)
        v = in[(((size_t)b * IC + ic) * HH + h) * WWW + w];
    float a0 = chunk8(v);
    float r1 = v - a0;
    float a1 = chunk8(r1);
    float a2 = r1 - a1;
    size_t base = (size_t)pix * 3072 + ic;
    g_xs3[base]        = a0;
    g_xs3[base + 1024] = a1;
    g_xs3[base + 2048] = a2;
}

// ====================== mma conv (round-7 structure, 8-bit chunks) ============
__global__ __launch_bounds__(256, 1) void conv_mma_kernel(const float* __restrict__ bc)
{
    extern __shared__ char smem[];
    const int tid  = threadIdx.x;
    const int wid  = tid >> 5;
    const int lane = tid & 31;
    const int mt = blockIdx.x;
    const int nt = blockIdx.y;
    const int b  = blockIdx.z;
    const int h0 = nt * 2;
    const int wm = wid & 1;
    const int wn = wid >> 1;

    float acc[4][4][4];
#pragma unroll
    for (int i = 0; i < 4; i++)
#pragma unroll
        for (int j = 0; j < 4; j++)
#pragma unroll
            for (int r = 0; r < 4; r++) acc[i][j][r] = 0.f;

    const char*  wsrc = (const char*)(g_wtc + (size_t)mt * NKK8 * 3072);
    const float* xb   = g_xs3 + (size_t)b * 66 * 66 * 3072;

    int bl_n[12], bl_u[12], bl_s[12];
#pragma unroll
    for (int j = 0; j < 12; j++) {
        int id = tid + j * 256;
        bl_s[j] = id >> 10;              // split 0..2
        bl_n[j] = (id >> 3) & 127;       // pixel 0..127
        bl_u[j] = id & 7;                // 4-float group within 32 k
    }

    auto issue = [&](int i, int st) {
        char* sa = smem + st * STAGE_BYTES;
        const char* asrc = wsrc + (size_t)i * 49152;
        unsigned au = (unsigned)__cvta_generic_to_shared(sa);
#pragma unroll
        for (int j = 0; j < 12; j++) {
            int off = (tid + j * 256) * 16;
            asm volatile("cp.async.cg.shared.global [%0], [%1], 16;"
                         :: "r"(au + off), "l"(asrc + off));
        }
        int t = i >> 5, c32 = i & 31;
        int kh = t / 3, kw = t - kh * 3;
        unsigned bu = au + B_OFF;
#pragma unroll
        for (int j = 0; j < 12; j++) {
            int n = bl_n[j];
            int pr = h0 + (n >> 6) + kh;
            int pc = (n & 63) + kw;
            const float* src = xb + (size_t)(pr * 66 + pc) * 3072 + (bl_s[j] << 10)
                                  + (c32 << 5) + (bl_u[j] << 2);
            unsigned dst = bu + bl_s[j] * 18432 + n * 144 + bl_u[j] * 16;
            asm volatile("cp.async.cg.shared.global [%0], [%1], 16;"
                         :: "r"(dst), "l"(src));
        }
        asm volatile("cp.async.commit_group;");
    };

    issue(0, 0);

    for (int i = 0; i < NITER; i++) {
        const int st = i & 1;
        if (i + 1 < NITER) {
            issue(i + 1, st ^ 1);
            asm volatile("cp.async.wait_group 1;");
        } else {
            asm volatile("cp.async.wait_group 0;");
        }
        __syncthreads();

        const char* sa = smem + st * STAGE_BYTES;
#pragma unroll
        for (int kk8 = 0; kk8 < 4; kk8++) {
            uint4 a[3][4];
#pragma unroll
            for (int s = 0; s < 3; s++)
#pragma unroll
                for (int mf = 0; mf < 4; mf++)
                    a[s][mf] = *(const uint4*)(sa +
                        (((kk8 * 3 + s) * 8 + (wm * 4 + mf)) * 512) + lane * 16);
            uint32_t bb[3][4][2];
#pragma unroll
            for (int s = 0; s < 3; s++)
#pragma unroll
                for (int nf = 0; nf < 4; nf++) {
                    const char* ba = sa + B_OFF + s * 18432
                        + (wn * 32 + nf * 8 + (lane >> 2)) * 144
                        + (kk8 * 8 + (lane & 3)) * 4;
                    bb[s][nf][0] = *(const uint32_t*)ba;
                    bb[s][nf][1] = *(const uint32_t*)(ba + 16);
                }
#pragma unroll
            for (int mf = 0; mf < 4; mf++)
#pragma unroll
                for (int nf = 0; nf < 4; nf++) {
                    MMA_TF32(acc[mf][nf], a[0][mf], bb[0][nf]);
                    MMA_TF32(acc[mf][nf], a[0][mf], bb[1][nf]);
                    MMA_TF32(acc[mf][nf], a[1][mf], bb[0][nf]);
                    MMA_TF32(acc[mf][nf], a[1][mf], bb[1][nf]);
                    MMA_TF32(acc[mf][nf], a[0][mf], bb[2][nf]);
                    MMA_TF32(acc[mf][nf], a[2][mf], bb[0][nf]);
                }
        }
        __syncthreads();
    }

#pragma unroll
    for (int mf = 0; mf < 4; mf++) {
        int oc0 = mt * 128 + wm * 64 + mf * 16 + (lane >> 2);
        float bias0 = bc[oc0];
        float bias8 = bc[oc0 + 8];
#pragma unroll
        for (int nf = 0; nf < 4; nf++) {
            int nl = wn * 32 + nf * 8 + (lane & 3) * 2;
            int h = h0 + (nl >> 6);
            int w = nl & 63;
            float2 v0, v1;
            v0.x = fmaxf(acc[mf][nf][0] + bias0, 0.f);
            v0.y = fmaxf(acc[mf][nf][1] + bias0, 0.f);
            v1.x = fmaxf(acc[mf][nf][2] + bias8, 0.f);
            v1.y = fmaxf(acc[mf][nf][3] + bias8, 0.f);
            *(float2*)(g_x + (((size_t)(b * OC + oc0) * HH + h) * WWW + w))     = v0;
            *(float2*)(g_x + (((size_t)(b * OC + oc0 + 8) * HH + h) * WWW + w)) = v1;
        }
    }
}

// ============ check kernel: sampled direct fp32 conv vs g_x ===================
// Working split -> max sample error ~6e-6; broken split ~1.5e-4+. Threshold 5e-5.
__global__ __launch_bounds__(128) void check_kernel(
    const float* __restrict__ in, const float* __restrict__ Wc,
    const float* __restrict__ bc)
{
    __shared__ float part[128];
    const int oc = blockIdx.x, b = blockIdx.y, tid = threadIdx.x;
    const int p = tid & 15, slice = tid >> 4;
    const int hs[4] = {0, 1, 31, 63};
    const int ws[4] = {0, 1, 32, 63};
    const int h = hs[p >> 2], w = ws[p & 3];

    float s = 0.f;
    const float* wrow0 = Wc + (size_t)oc * IC * 9;
    for (int ic = slice * 128; ic < slice * 128 + 128; ic++) {
        const float* wrow = wrow0 + (size_t)ic * 9;
        const float* irow = in + ((size_t)(b * IC + ic) * HH) * WWW;
#pragma unroll
        for (int kh = 0; kh < 3; kh++) {
            int ih = h - 1 + kh;
            if (ih < 0 || ih >= HH) continue;
#pragma unroll
            for (int kw = 0; kw < 3; kw++) {
                int iw = w - 1 + kw;
                if (iw < 0 || iw >= WWW) continue;
                s += wrow[kh * 3 + kw] * irow[ih * WWW + iw];
            }
        }
    }
    part[tid] = s;
    __syncthreads();
    if (tid < 16) {
        float tot = 0.f;
        for (int sl = 0; sl < 8; sl++) tot += part[sl * 16 + tid];
        float v = fmaxf(tot + bc[oc], 0.f);
        float ref = g_x[(((size_t)(b * OC + oc) * HH) + h) * WWW + w];
        float rel = fabsf(v - ref) / fmaxf(fabsf(v), 1.0f);
        if (rel > 5e-5f) atomicOr(&g_flag, 1);
    }
}

// ================= fallback path (round-3 validated, gated) ===================
__global__ __launch_bounds__(256) void prep_weights(const float* __restrict__ Wc)
{
    if (g_flag == 0) return;
    int idx = blockIdx.x * 256 + threadIdx.x;
    if (idx >= NCHUNK * NOCT * WNUM) return;
    int c  = idx / (NOCT * WNUM);
    int r  = idx - c * (NOCT * WNUM);
    int ot = r / WNUM;
    int e  = r - ot * WNUM;
    int icl = e / 288;
    int e2  = e - icl * 288;
    int k   = e2 >> 5;
    int ocl = e2 & 31;
    g_wr[idx] = Wc[((size_t)(ot * 32 + ocl) * IC + c * ICC + icl) * 9 + k];
}

__global__ __launch_bounds__(256) void prep_input(const float* __restrict__ in)
{
    if (g_flag == 0) return;
    int idx = blockIdx.x * 256 + threadIdx.x;
    const int TOT = NB * IC * 66 * IPITCH;
    if (idx >= TOT) return;
    int bi  = idx / (66 * IPITCH);
    int r   = idx - bi * (66 * IPITCH);
    int row = r / IPITCH;
    int col = r - row * IPITCH;
    int h   = row - 1;
    int w   = col - 1;
    float v = 0.f;
    if (h >= 0 && h < HH && w >= 0 && w < WWW && col < 66)
        v = in[((size_t)bi * HH + h) * WWW + w];
    g_ipad[idx] = v;
}

__global__ __launch_bounds__(128, 3) void conv_ffma2_kernel(const float* __restrict__ bc)
{
    if (g_flag == 0) return;
    __shared__ float sW[2][WNUM];
    __shared__ float sIn[2][INUM];

    const int oc0 = blockIdx.x * OCT;
    const int h0  = blockIdx.y * HT;
    const int b   = blockIdx.z;
    const int tid = threadIdx.x;

    const int tz  = tid >> 5;
    const int to0 = ((tid >> 3) & 3) * 8;
    const int tw0 = (tid & 7) * 8;

    const unsigned sW_u[2] = {
        (unsigned)__cvta_generic_to_shared(&sW[0][0]),
        (unsigned)__cvta_generic_to_shared(&sW[1][0]) };
    const unsigned sIn_u[2] = {
        (unsigned)__cvta_generic_to_shared(&sIn[0][0]),
        (unsigned)__cvta_generic_to_shared(&sIn[1][0]) };

    const float* wbase = g_wr + (size_t)blockIdx.x * WNUM;
    int i_icl[7], i_off[7];
#pragma unroll
    for (int s = 0; s < 7; s++) {
        int idx4 = tid + s * 128;
        int icl  = idx4 / 102;
        int r    = idx4 - icl * 102;
        int row  = r / 17;
        int c4   = r - row * 17;
        i_icl[s] = icl;
        i_off[s] = (h0 + row) * IPITCH + c4 * 4;
    }

    unsigned long long acc2[4][8];
#pragma unroll
    for (int p = 0; p < 4; p++)
#pragma unroll
        for (int j = 0; j < 8; j++) acc2[p][j] = 0ull;

    auto issue_chunk = [&](int kc, int bu) {
        const unsigned sWu  = sW_u[bu];
        const unsigned sInu = sIn_u[bu];
        const float* ws = wbase + (size_t)kc * (NOCT * WNUM);
#pragma unroll
        for (int s = 0; s < 5; s++) {
            int idx4 = tid + s * 128;
            if (idx4 < WNUM / 4) {
                const float* g = ws + idx4 * 4;
                asm volatile("cp.async.cg.shared.global [%0], [%1], 16;"
                             :: "r"(sWu + (unsigned)(idx4 * 16)), "l"(g));
            }
        }
        const int ic0 = kc * ICC;
#pragma unroll
        for (int s = 0; s < 7; s++) {
            int idx4 = tid + s * 128;
            if (idx4 < INUM / 4) {
                const float* g = g_ipad +
                    ((size_t)(b * IC + ic0 + i_icl[s]) * 66) * IPITCH + i_off[s];
                asm volatile("cp.async.cg.shared.global [%0], [%1], 16;"
                             :: "r"(sInu + (unsigned)(idx4 * 16)), "l"(g));
            }
        }
        asm volatile("cp.async.commit_group;");
    };

    issue_chunk(0, 0);

    for (int kc = 0; kc < NCHUNK; kc++) {
        const int cur = kc & 1;
        if (kc < NCHUNK - 1) {
            issue_chunk(kc + 1, cur ^ 1);
            asm volatile("cp.async.wait_group 1;");
        } else {
            asm volatile("cp.async.wait_group 0;");
        }
        __syncthreads();

        const float* W_ = sW[cur];
        const float* I_ = sIn[cur];

#pragma unroll 1
        for (int ic = 0; ic < ICC; ic++) {
            const float* irow = I_ + (ic * 6 + tz) * IPITCH + tw0;
            const float* wrow = W_ + ic * 9 * OCT + to0;
#pragma unroll
            for (int kh = 0; kh < 3; kh++) {
                float4 f0 = *(const float4*)(irow + kh * IPITCH);
                float4 f1 = *(const float4*)(irow + kh * IPITCH + 4);
                float4 f2 = *(const float4*)(irow + kh * IPITCH + 8);
                unsigned long long ib[10];
                ib[0] = bc2(f0.x); ib[1] = bc2(f0.y); ib[2] = bc2(f0.z); ib[3] = bc2(f0.w);
                ib[4] = bc2(f1.x); ib[5] = bc2(f1.y); ib[6] = bc2(f1.z); ib[7] = bc2(f1.w);
                ib[8] = bc2(f2.x); ib[9] = bc2(f2.y);
#pragma unroll
                for (int kw = 0; kw < 3; kw++) {
                    const ulonglong2* wp =
                        (const ulonglong2*)(wrow + (kh * 3 + kw) * OCT);
                    ulonglong2 wa = wp[0];
                    ulonglong2 wb = wp[1];
#pragma unroll
                    for (int j = 0; j < 8; j++) {
                        FMA2(acc2[0][j], wa.x, ib[j + kw], acc2[0][j]);
                        FMA2(acc2[1][j], wa.y, ib[j + kw], acc2[1][j]);
                        FMA2(acc2[2][j], wb.x, ib[j + kw], acc2[2][j]);
                        FMA2(acc2[3][j], wb.y, ib[j + kw], acc2[3][j]);
                    }
                }
            }
        }
        __syncthreads();
    }

    const int h = h0 + tz;
#pragma unroll
    for (int p = 0; p < 4; p++) {
#pragma unroll
        for (int s = 0; s < 2; s++) {
            int oc = oc0 + to0 + 2 * p + s;
            float bias = bc[oc];
            float* op = &g_x[((size_t)(b * OC + oc) * HH + h) * WWW + tw0];
#pragma unroll
            for (int j = 0; j < 8; j++) {
                float v = (s == 0 ? lo32(acc2[p][j]) : hi32(acc2[p][j])) + bias;
                op[j] = v > 0.f ? v : 0.f;
            }
        }
    }
}

// ============ Kernel 2: heads (round-3 validated 64-thread version) ===========
__global__ __launch_bounds__(64) void heads_kernel(
    const float* __restrict__ meta,
    const float* __restrict__ Wcls, const float* __restrict__ bcls,
    const float* __restrict__ Wbb,  const float* __restrict__ bbb)
{
    __shared__ float sw[512 * 20];
    __shared__ float sb[20];

    const int h = blockIdx.x, b = blockIdx.y, tid = threadIdx.x;

    for (int idx = tid; idx < 512 * 20; idx += 64) {
        int c = idx / 20, o = idx - c * 20;
        sw[idx] = (o < 4) ? Wcls[o * 512 + c] : Wbb[(o - 4) * 512 + c];
    }
    if (tid < 20) sb[tid] = (tid < 4) ? bcls[tid] : bbb[tid - 4];
    __syncthreads();

    const int w = tid;
    float acc[20];
#pragma unroll
    for (int o = 0; o < 20; o++) acc[o] = 0.f;

    const float* xp = g_x + ((size_t)(b * OC) * HH + h) * WWW + w;
    for (int c = 0; c < 512; c++) {
        float xv = xp[(size_t)c * HH * WWW];
        const float4* wp = reinterpret_cast<const float4*>(&sw[c * 20]);
        float4 w0 = wp[0], w1 = wp[1], w2 = wp[2], w3 = wp[3], w4 = wp[4];
        acc[0]  = fmaf(xv, w0.x, acc[0]);  acc[1]  = fmaf(xv, w0.y, acc[1]);
        acc[2]  = fmaf(xv, w0.z, acc[2]);  acc[3]  = fmaf(xv, w0.w, acc[3]);
        acc[4]  = fmaf(xv, w1.x, acc[4]);  acc[5]  = fmaf(xv, w1.y, acc[5]);
        acc[6]  = fmaf(xv, w1.z, acc[6]);  acc[7]  = fmaf(xv, w1.w, acc[7]);
        acc[8]  = fmaf(xv, w2.x, acc[8]);  acc[9]  = fmaf(xv, w2.y, acc[9]);
        acc[10] = fmaf(xv, w2.z, acc[10]); acc[11] = fmaf(xv, w2.w, acc[11]);
        acc[12] = fmaf(xv, w3.x, acc[12]); acc[13] = fmaf(xv, w3.y, acc[13]);
        acc[14] = fmaf(xv, w3.z, acc[14]); acc[15] = fmaf(xv, w3.w, acc[15]);
        acc[16] = fmaf(xv, w4.x, acc[16]); acc[17] = fmaf(xv, w4.y, acc[17]);
        acc[18] = fmaf(xv, w4.z, acc[18]); acc[19] = fmaf(xv, w4.w, acc[19]);
    }

    float s[4];
#pragma unroll
    for (int a = 0; a < 4; a++) s[a] = acc[a] + sb[a];
    float prob[4];
#pragma unroll
    for (int a = 0; a < 4; a++) {
        int p = a ^ 2;
        float m  = fmaxf(s[a], s[p]);
        float ea = expf(s[a] - m);
        float eb = expf(s[p] - m);
        prob[a]  = ea / (ea + eb);
    }

    const float im_h = meta[b * 3 + 0];
    const float im_w = meta[b * 3 + 1];
    const float scl  = meta[b * 3 + 2];
    const float minsz = 16.f * scl;

    const int base = b * NA + (h * 64 + w) * 4;
#pragma unroll
    for (int a = 0; a < 4; a++) {
        float wa = (float)(64 << a);
        float cx = w * 16.f + 8.f;
        float cy = h * 16.f + 8.f;
        float d0 = acc[4 + a * 4 + 0] + sb[4 + a * 4 + 0];
        float d1 = acc[4 + a * 4 + 1] + sb[4 + a * 4 + 1];
        float d2 = acc[4 + a * 4 + 2] + sb[4 + a * 4 + 2];
        float d3 = acc[4 + a * 4 + 3] + sb[4 + a * 4 + 3];
        float pcx = d0 * wa + cx, pcy = d1 * wa + cy;
        float pw  = expf(d2) * wa, ph = expf(d3) * wa;
        float x1 = pcx - 0.5f * pw, y1 = pcy - 0.5f * ph;
        float x2 = pcx + 0.5f * pw, y2 = pcy + 0.5f * ph;
        x1 = fminf(fmaxf(x1, 0.f), im_w - 1.f);
        x2 = fminf(fmaxf(x2, 0.f), im_w - 1.f);
        y1 = fminf(fmaxf(y1, 0.f), im_h - 1.f);
        y2 = fminf(fmaxf(y2, 0.f), im_h - 1.f);
        bool keep = (x2 - x1 + 1.f >= minsz) && (y2 - y1 + 1.f >= minsz);
        g_scores[base + a] = keep ? prob[a] : -INFINITY;
        g_boxes[base + a]  = make_float4(x1, y1, x2, y2);
    }
}

// ================= Kernel 3: exact top-6000 mark (per image) ==================
__global__ __launch_bounds__(1024) void topk_kernel()
{
    const int b   = blockIdx.x;
    const int tid = threadIdx.x;
    float* scores = g_scores + b * NA;

    unsigned key[16];
    const int i0 = tid * 16;
#pragma unroll
    for (int i = 0; i < 16; i++) key[i] = ordkey(scores[i0 + i]);

    __shared__ int wsum[32];
    __shared__ int s_total;
    const int lane = tid & 31, wid = tid >> 5;

    auto count_ge = [&](unsigned cand) -> int {
        int local = 0;
#pragma unroll
        for (int i = 0; i < 16; i++) local += (key[i] >= cand) ? 1 : 0;
        for (int off = 16; off; off >>= 1)
            local += __shfl_down_sync(0xFFFFFFFFu, local, off);
        if (lane == 0) wsum[wid] = local;
        __syncthreads();
        if (tid == 0) {
            int st = 0;
            for (int k = 0; k < 32; k++) st += wsum[k];
            s_total = st;
        }
        __syncthreads();
        int r = s_total;
        __syncthreads();
        return r;
    };

    unsigned thr = 0;
    for (int bit = 31; bit >= 0; bit--) {
        unsigned cand = thr | (1u << bit);
        if (count_ge(cand) >= PRE_NMS_K) thr = cand;
    }
    const int n_gt = count_ge(thr + 1u);
    const int need = PRE_NMS_K - n_gt;

    int my_eq = 0;
#pragma unroll
    for (int i = 0; i < 16; i++) my_eq += (key[i] == thr) ? 1 : 0;

    int v = my_eq;
    for (int off = 1; off < 32; off <<= 1) {
        int tt = __shfl_up_sync(0xFFFFFFFFu, v, off);
        if (lane >= off) v += tt;
    }
    __syncthreads();
    if (lane == 31) wsum[wid] = v;
    __syncthreads();
    if (wid == 0) {
        int sv = wsum[lane];
        for (int off = 1; off < 32; off <<= 1) {
            int tt = __shfl_up_sync(0xFFFFFFFFu, sv, off);
            if (lane >= off) sv += tt;
        }
        wsum[lane] = sv;
    }
    __syncthreads();
    int rank = v - my_eq + (wid ? wsum[wid - 1] : 0);

#pragma unroll
    for (int i = 0; i < 16; i++) {
        if (key[i] == thr) {
            if (rank >= need) scores[i0 + i] = -INFINITY;
            rank++;
        } else if (key[i] < thr) {
            scores[i0 + i] = -INFINITY;
        }
    }
}

// ===================== Kernel 4: exact greedy NMS (per image) =================
__global__ __launch_bounds__(512) void nms_kernel(float* __restrict__ out)
{
    const int b   = blockIdx.x;
    const int tid = threadIdx.x;
    const float4* boxes = g_boxes + b * NA;

    float sc[32];
    const int i0 = tid * 32;
#pragma unroll
    for (int i = 0; i < 32; i++) sc[i] = g_scores[b * NA + i0 + i];

    __shared__ unsigned long long swm[16];
    __shared__ unsigned long long s_best;
    __shared__ float4 s_box;
    __shared__ float  s_area;
    __shared__ int    s_firstj;

    const int lane = tid & 31, wid = tid >> 5;

    for (int it = 0; it < POST_NMS_K; it++) {
        unsigned long long loc = ((unsigned long long)ORD_NEG_INF << 32);
#pragma unroll
        for (int i = 0; i < 32; i++) {
            unsigned long long kk =
                ((unsigned long long)ordkey(sc[i]) << 32) |
                (unsigned)(65535 - (i0 + i));
            loc = (kk > loc) ? kk : loc;
        }
        for (int off = 16; off; off >>= 1) {
            unsigned long long o = __shfl_down_sync(0xFFFFFFFFu, loc, off);
            loc = (o > loc) ? o : loc;
        }
        if (lane == 0) swm[wid] = loc;
        __syncthreads();
        if (tid < 16) {
            unsigned long long vv = swm[tid];
            for (int off = 8; off; off >>= 1) {
                unsigned long long o = __shfl_down_sync(0x0000FFFFu, vv, off);
                vv = (o > vv) ? o : vv;
            }
            if (tid == 0) s_best = vv;
        }
        __syncthreads();

        if (tid == 0) {
            unsigned long long best = s_best;
            unsigned keypart = (unsigned)(best >> 32);
            int j;
            if (keypart == ORD_NEG_INF && it > 0) j = s_firstj;
            else j = 65535 - (int)(best & 0xFFFFFFFFull);
            if (it == 0) s_firstj = j;
            float4 bx = boxes[j];
            s_box  = bx;
            s_area = (bx.z - bx.x + 1.f) * (bx.w - bx.y + 1.f);
            float* o = out + (size_t)(b * POST_NMS_K + it) * 5;
            o[0] = (float)b; o[1] = bx.x; o[2] = bx.y; o[3] = bx.z; o[4] = bx.w;
        }
        __syncthreads();

        const float4 jb = s_box;
        const float  ja = s_area;
#pragma unroll 4
        for (int i = 0; i < 32; i++) {
            float4 bb = boxes[i0 + i];
            float xx1 = fmaxf(jb.x, bb.x);
            float yy1 = fmaxf(jb.y, bb.y);
            float xx2 = fminf(jb.z, bb.z);
            float yy2 = fminf(jb.w, bb.w);
            float iw  = fmaxf(xx2 - xx1 + 1.f, 0.f);
            float ih  = fmaxf(yy2 - yy1 + 1.f, 0.f);
            float inter = iw * ih;
            float area  = (bb.z - bb.x + 1.f) * (bb.w - bb.y + 1.f);
            float iou   = inter / (ja + area - inter);
            if (iou > 0.7f) sc[i] = -INFINITY;
        }
    }
}

// ================================ launcher ====================================
extern "C" void kernel_launch(void* const* d_in, const int* in_sizes, int n_in,
                              void* d_out, int out_size)
{
    const float* feat = (const float*)d_in[0];
    const float* meta = (const float*)d_in[1];
    const float* Wc   = (const float*)d_in[3];
    const float* bc   = (const float*)d_in[4];
    const float* Wcls = (const float*)d_in[5];
    const float* bcls = (const float*)d_in[6];
    const float* Wbb  = (const float*)d_in[7];
    const float* bbb  = (const float*)d_in[8];
    float* out = (float*)d_out;

    cudaFuncSetAttribute(conv_mma_kernel,
                         cudaFuncAttributeMaxDynamicSharedMemorySize, CONV_SMEM);

    zero_flag_kernel<<<1, 1>>>();
    // --- mma path: 8-bit (bf16-exact) 3-chunk splits, exact decomposition ---
    prep_w_tc<<<(4 * NKK8 * 1024 + 255) / 256, 256>>>(Wc);
    prep_x_tc<<<(NB * 66 * 66 * 1024 + 255) / 256, 256>>>(feat);
    conv_mma_kernel<<<dim3(4, 32, 2), 256, CONV_SMEM>>>(bc);
    // --- verify samples; set g_flag if mma conv is wrong ---
    check_kernel<<<dim3(512, 2), 128>>>(feat, Wc, bc);
    // --- validated fallback path (runs only if flag set) ---
    prep_weights<<<(NCHUNK * NOCT * WNUM + 255) / 256, 256>>>(Wc);
    prep_input<<<(NB * IC * 66 * IPITCH + 255) / 256, 256>>>(feat);
    conv_ffma2_kernel<<<dim3(16, 16, 2), 128>>>(bc);
    // --- validated tail (64-thread heads) ---
    heads_kernel<<<dim3(64, 2), 64>>>(meta, Wcls, bcls, Wbb, bbb);
    topk_kernel<<<2, 1024>>>();
    nms_kernel<<<2, 512>>>(out);
}

// round 14
// speedup vs baseline: 1.7184x; 1.2184x over previous
#include <cuda_runtime.h>
#include <stdint.h>
#include <math.h>

#define IC 1024
#define OC 512
#define HH 64
#define WWW 64
#define NB 2
#define NA 16384
#define PRE_NMS_K 6000
#define POST_NMS_K 300

// ---- mma conv params ----
#define NKK8 1152                 // K/8 = 9216/8 (tap-major: t*1024+ic)
#define NITER 288                 // K stages of 32 (9 taps x 32 ic-chunks)
#define STAGE_BYTES 104448        // A 49152 + B 55296
#define B_OFF 49152
#define CONV_SMEM (2 * STAGE_BYTES)   // 208896

// ---- ffma2 fallback conv params (round-3 validated) ----
#define ICC 8
#define OCT 32
#define HT 4
#define IPITCH 68
#define WNUM (ICC*9*OCT)
#define INUM (ICC*6*IPITCH)
#define NCHUNK (IC/ICC)
#define NOCT (OC/OCT)

// ---------------- scratch (static device allocations, allowed) ----------------
__device__ float g_x[NB * OC * HH * WWW];
__device__ float g_wtc[4 * NKK8 * 3 * 8 * 32 * 4];
__device__ float g_xs3[NB * 66 * 66 * 3 * 1024];
__device__ float g_wr[NCHUNK * NOCT * WNUM];
__device__ float g_ipad[NB * IC * 66 * IPITCH];
__device__ float g_scores[NB * NA];
__device__ float4 g_boxes[NB * NA];
__device__ int   g_flag;

__device__ __forceinline__ unsigned ordkey(float f) {
    unsigned u = __float_as_uint(f);
    return (u & 0x80000000u) ? ~u : (u | 0x80000000u);
}
#define ORD_NEG_INF 0x007FFFFFu

// 8-significand-bit chunks (bf16-exact). Exact 3-term decomposition; each
// chunk survives any HW input truncation >= 8 bits.
__device__ __forceinline__ float chunk8(float v) {
    return __uint_as_float(__float_as_uint(v) & 0xFFFF0000u);
}

#define MMA_TF32(c, a, b) \
    asm volatile("mma.sync.aligned.m16n8k8.row.col.f32.tf32.tf32.f32 " \
        "{%0,%1,%2,%3}, {%4,%5,%6,%7}, {%8,%9}, {%0,%1,%2,%3};" \
        : "+f"((c)[0]), "+f"((c)[1]), "+f"((c)[2]), "+f"((c)[3]) \
        : "r"((a).x), "r"((a).y), "r"((a).z), "r"((a).w), \
          "r"((b)[0]), "r"((b)[1]))

// ---- packed f32x2 helpers (fallback conv) ----
__device__ __forceinline__ unsigned long long bc2(float f) {
    unsigned long long r; unsigned u = __float_as_uint(f);
    asm("mov.b64 %0, {%1, %1};" : "=l"(r) : "r"(u));
    return r;
}
#define FMA2(d, a, b, c) \
    asm("fma.rn.f32x2 %0, %1, %2, %3;" : "=l"(d) : "l"(a), "l"(b), "l"(c))
__device__ __forceinline__ float lo32(unsigned long long v) {
    return __uint_as_float((unsigned)v);
}
__device__ __forceinline__ float hi32(unsigned long long v) {
    return __uint_as_float((unsigned)(v >> 32));
}

__global__ void zero_flag_kernel() { g_flag = 0; }

// ======================= mma path pre-passes ==================================
// A-fragment per PTX ISA m16n8k8.tf32:
//   r0:(m,k) r1:(m+8,k) r2:(m,k+4) r3:(m+8,k+4); m=lam>>2, k=lam&3
__global__ __launch_bounds__(256) void prep_w_tc(const float* __restrict__ Wc)
{
    int idx = blockIdx.x * 256 + threadIdx.x;
    if (idx >= 4 * NKK8 * 8 * 32 * 4) return;
    int r   = idx & 3;
    int lam = (idx >> 2) & 31;
    int mf  = (idx >> 7) & 7;
    int rest = idx >> 10;
    int kk8 = rest % NKK8;
    int mt  = rest / NKK8;
    int oc = mt * 128 + mf * 16 + (lam >> 2) + (r & 1) * 8;
    int t  = kk8 / 128;
    int ic = (kk8 % 128) * 8 + (lam & 3) + (r >> 1) * 4;
    float v  = Wc[((size_t)oc * IC + ic) * 9 + t];
    float a0 = chunk8(v);
    float r1 = v - a0;
    float a1 = chunk8(r1);
    float a2 = r1 - a1;
    size_t base = (size_t)(mt * NKK8 + kk8) * 3072 + mf * 128 + lam * 4 + r;
    g_wtc[base]        = a0;
    g_wtc[base + 1024] = a1;
    g_wtc[base + 2048] = a2;
}

__global__ __launch_bounds__(256) void prep_x_tc(const float* __restrict__ in)
{
    int idx = blockIdx.x * 256 + threadIdx.x;
    if (idx >= NB * 66 * 66 * 1024) return;
    int ic = idx & 1023;
    int pix = idx >> 10;
    int pc = pix % 66;
    int rest2 = pix / 66;
    int pr = rest2 % 66;
    int b  = rest2 / 66;
    int h = pr - 1, w = pc - 1;
    float v = 0.f;
    if (h >= 0 && h < HH && w >= 0 && w < WWW)
        v = in[(((size_t)b * IC + ic) * HH + h) * WWW + w];
    float a0 = chunk8(v);
    float r1 = v - a0;
    float a1 = chunk8(r1);
    float a2 = r1 - a1;
    size_t base = (size_t)pix * 3072 + ic;
    g_xs3[base]        = a0;
    g_xs3[base + 1024] = a1;
    g_xs3[base + 2048] = a2;
}

// ===== mma conv: 8-bit chunks + accumulator drains (anti truncation-bias) =====
__global__ __launch_bounds__(256, 1) void conv_mma_kernel(const float* __restrict__ bc)
{
    extern __shared__ char smem[];
    const int tid  = threadIdx.x;
    const int wid  = tid >> 5;
    const int lane = tid & 31;
    const int mt = blockIdx.x;
    const int nt = blockIdx.y;
    const int b  = blockIdx.z;
    const int h0 = nt * 2;
    const int wm = wid & 1;
    const int wn = wid >> 1;

    float acc[4][4][4];     // in-MMA accumulator (short chains)
    float accR[4][4][4];    // RN-drained master accumulator
#pragma unroll
    for (int i = 0; i < 4; i++)
#pragma unroll
        for (int j = 0; j < 4; j++)
#pragma unroll
            for (int r = 0; r < 4; r++) { acc[i][j][r] = 0.f; accR[i][j][r] = 0.f; }

    const char*  wsrc = (const char*)(g_wtc + (size_t)mt * NKK8 * 3072);
    const float* xb   = g_xs3 + (size_t)b * 66 * 66 * 3072;

    int bl_n[12], bl_u[12], bl_s[12];
#pragma unroll
    for (int j = 0; j < 12; j++) {
        int id = tid + j * 256;
        bl_s[j] = id >> 10;
        bl_n[j] = (id >> 3) & 127;
        bl_u[j] = id & 7;
    }

    auto issue = [&](int i, int st) {
        char* sa = smem + st * STAGE_BYTES;
        const char* asrc = wsrc + (size_t)i * 49152;
        unsigned au = (unsigned)__cvta_generic_to_shared(sa);
#pragma unroll
        for (int j = 0; j < 12; j++) {
            int off = (tid + j * 256) * 16;
            asm volatile("cp.async.cg.shared.global [%0], [%1], 16;"
                         :: "r"(au + off), "l"(asrc + off));
        }
        int t = i >> 5, c32 = i & 31;
        int kh = t / 3, kw = t - kh * 3;
        unsigned bu = au + B_OFF;
#pragma unroll
        for (int j = 0; j < 12; j++) {
            int n = bl_n[j];
            int pr = h0 + (n >> 6) + kh;
            int pc = (n & 63) + kw;
            const float* src = xb + (size_t)(pr * 66 + pc) * 3072 + (bl_s[j] << 10)
                                  + (c32 << 5) + (bl_u[j] << 2);
            unsigned dst = bu + bl_s[j] * 18432 + n * 144 + bl_u[j] * 16;
            asm volatile("cp.async.cg.shared.global [%0], [%1], 16;"
                         :: "r"(dst), "l"(src));
        }
        asm volatile("cp.async.commit_group;");
    };

    issue(0, 0);

    for (int i = 0; i < NITER; i++) {
        const int st = i & 1;
        if (i + 1 < NITER) {
            issue(i + 1, st ^ 1);
            asm volatile("cp.async.wait_group 1;");
        } else {
            asm volatile("cp.async.wait_group 0;");
        }
        __syncthreads();

        const char* sa = smem + st * STAGE_BYTES;
#pragma unroll
        for (int kk8 = 0; kk8 < 4; kk8++) {
            uint32_t bb[3][4][2];
#pragma unroll
            for (int s = 0; s < 3; s++)
#pragma unroll
                for (int nf = 0; nf < 4; nf++) {
                    const char* ba = sa + B_OFF + s * 18432
                        + (wn * 32 + nf * 8 + (lane >> 2)) * 144
                        + (kk8 * 8 + (lane & 3)) * 4;
                    bb[s][nf][0] = *(const uint32_t*)ba;
                    bb[s][nf][1] = *(const uint32_t*)(ba + 16);
                }
            // s grouped to cap live A registers (16 at a time)
            {
                uint4 a[4];
#pragma unroll
                for (int mf = 0; mf < 4; mf++)
                    a[mf] = *(const uint4*)(sa +
                        (((kk8 * 3 + 0) * 8 + (wm * 4 + mf)) * 512) + lane * 16);
#pragma unroll
                for (int mf = 0; mf < 4; mf++)
#pragma unroll
                    for (int nf = 0; nf < 4; nf++) {
                        MMA_TF32(acc[mf][nf], a[mf], bb[0][nf]);
                        MMA_TF32(acc[mf][nf], a[mf], bb[1][nf]);
                        MMA_TF32(acc[mf][nf], a[mf], bb[2][nf]);
                    }
            }
            {
                uint4 a[4];
#pragma unroll
                for (int mf = 0; mf < 4; mf++)
                    a[mf] = *(const uint4*)(sa +
                        (((kk8 * 3 + 1) * 8 + (wm * 4 + mf)) * 512) + lane * 16);
#pragma unroll
                for (int mf = 0; mf < 4; mf++)
#pragma unroll
                    for (int nf = 0; nf < 4; nf++) {
                        MMA_TF32(acc[mf][nf], a[mf], bb[0][nf]);
                        MMA_TF32(acc[mf][nf], a[mf], bb[1][nf]);
                    }
            }
            {
                uint4 a[4];
#pragma unroll
                for (int mf = 0; mf < 4; mf++)
                    a[mf] = *(const uint4*)(sa +
                        (((kk8 * 3 + 2) * 8 + (wm * 4 + mf)) * 512) + lane * 16);
#pragma unroll
                for (int mf = 0; mf < 4; mf++)
#pragma unroll
                    for (int nf = 0; nf < 4; nf++)
                        MMA_TF32(acc[mf][nf], a[mf], bb[0][nf]);
            }
        }
        __syncthreads();

        // drain: every 16 iterations, fold short MMA chain into RN accumulator
        if ((i & 15) == 15) {
#pragma unroll
            for (int mf = 0; mf < 4; mf++)
#pragma unroll
                for (int nf = 0; nf < 4; nf++)
#pragma unroll
                    for (int r = 0; r < 4; r++) {
                        accR[mf][nf][r] += acc[mf][nf][r];
                        acc[mf][nf][r] = 0.f;
                    }
        }
    }

#pragma unroll
    for (int mf = 0; mf < 4; mf++) {
        int oc0 = mt * 128 + wm * 64 + mf * 16 + (lane >> 2);
        float bias0 = bc[oc0];
        float bias8 = bc[oc0 + 8];
#pragma unroll
        for (int nf = 0; nf < 4; nf++) {
            int nl = wn * 32 + nf * 8 + (lane & 3) * 2;
            int h = h0 + (nl >> 6);
            int w = nl & 63;
            float2 v0, v1;
            v0.x = fmaxf(accR[mf][nf][0] + acc[mf][nf][0] + bias0, 0.f);
            v0.y = fmaxf(accR[mf][nf][1] + acc[mf][nf][1] + bias0, 0.f);
            v1.x = fmaxf(accR[mf][nf][2] + acc[mf][nf][2] + bias8, 0.f);
            v1.y = fmaxf(accR[mf][nf][3] + acc[mf][nf][3] + bias8, 0.f);
            *(float2*)(g_x + (((size_t)(b * OC + oc0) * HH + h) * WWW + w))     = v0;
            *(float2*)(g_x + (((size_t)(b * OC + oc0 + 8) * HH + h) * WWW + w)) = v1;
        }
    }
}

// ============ check kernel: sampled direct fp32 conv vs g_x ===================
// Drained conv -> errors ~1e-5; structural/pure-tf32 failures >= 5e-4.
// Threshold 2e-4 separates the classes.
__global__ __launch_bounds__(128) void check_kernel(
    const float* __restrict__ in, const float* __restrict__ Wc,
    const float* __restrict__ bc)
{
    __shared__ float part[128];
    const int oc = blockIdx.x, b = blockIdx.y, tid = threadIdx.x;
    const int p = tid & 15, slice = tid >> 4;
    const int hs[4] = {0, 1, 31, 63};
    const int ws[4] = {0, 1, 32, 63};
    const int h = hs[p >> 2], w = ws[p & 3];

    float s = 0.f;
    const float* wrow0 = Wc + (size_t)oc * IC * 9;
    for (int ic = slice * 128; ic < slice * 128 + 128; ic++) {
        const float* wrow = wrow0 + (size_t)ic * 9;
        const float* irow = in + ((size_t)(b * IC + ic) * HH) * WWW;
#pragma unroll
        for (int kh = 0; kh < 3; kh++) {
            int ih = h - 1 + kh;
            if (ih < 0 || ih >= HH) continue;
#pragma unroll
            for (int kw = 0; kw < 3; kw++) {
                int iw = w - 1 + kw;
                if (iw < 0 || iw >= WWW) continue;
                s += wrow[kh * 3 + kw] * irow[ih * WWW + iw];
            }
        }
    }
    part[tid] = s;
    __syncthreads();
    if (tid < 16) {
        float tot = 0.f;
        for (int sl = 0; sl < 8; sl++) tot += part[sl * 16 + tid];
        float v = fmaxf(tot + bc[oc], 0.f);
        float ref = g_x[(((size_t)(b * OC + oc) * HH) + h) * WWW + w];
        float rel = fabsf(v - ref) / fmaxf(fabsf(v), 1.0f);
        if (rel > 2e-4f) atomicOr(&g_flag, 1);
    }
}

// ================= fallback path (round-3 validated, gated) ===================
__global__ __launch_bounds__(256) void prep_weights(const float* __restrict__ Wc)
{
    if (g_flag == 0) return;
    int idx = blockIdx.x * 256 + threadIdx.x;
    if (idx >= NCHUNK * NOCT * WNUM) return;
    int c  = idx / (NOCT * WNUM);
    int r  = idx - c * (NOCT * WNUM);
    int ot = r / WNUM;
    int e  = r - ot * WNUM;
    int icl = e / 288;
    int e2  = e - icl * 288;
    int k   = e2 >> 5;
    int ocl = e2 & 31;
    g_wr[idx] = Wc[((size_t)(ot * 32 + ocl) * IC + c * ICC + icl) * 9 + k];
}

__global__ __launch_bounds__(256) void prep_input(const float* __restrict__ in)
{
    if (g_flag == 0) return;
    int idx = blockIdx.x * 256 + threadIdx.x;
    const int TOT = NB * IC * 66 * IPITCH;
    if (idx >= TOT) return;
    int bi  = idx / (66 * IPITCH);
    int r   = idx - bi * (66 * IPITCH);
    int row = r / IPITCH;
    int col = r - row * IPITCH;
    int h   = row - 1;
    int w   = col - 1;
    float v = 0.f;
    if (h >= 0 && h < HH && w >= 0 && w < WWW && col < 66)
        v = in[((size_t)bi * HH + h) * WWW + w];
    g_ipad[idx] = v;
}

__global__ __launch_bounds__(128, 3) void conv_ffma2_kernel(const float* __restrict__ bc)
{
    if (g_flag == 0) return;
    __shared__ float sW[2][WNUM];
    __shared__ float sIn[2][INUM];

    const int oc0 = blockIdx.x * OCT;
    const int h0  = blockIdx.y * HT;
    const int b   = blockIdx.z;
    const int tid = threadIdx.x;

    const int tz  = tid >> 5;
    const int to0 = ((tid >> 3) & 3) * 8;
    const int tw0 = (tid & 7) * 8;

    const unsigned sW_u[2] = {
        (unsigned)__cvta_generic_to_shared(&sW[0][0]),
        (unsigned)__cvta_generic_to_shared(&sW[1][0]) };
    const unsigned sIn_u[2] = {
        (unsigned)__cvta_generic_to_shared(&sIn[0][0]),
        (unsigned)__cvta_generic_to_shared(&sIn[1][0]) };

    const float* wbase = g_wr + (size_t)blockIdx.x * WNUM;
    int i_icl[7], i_off[7];
#pragma unroll
    for (int s = 0; s < 7; s++) {
        int idx4 = tid + s * 128;
        int icl  = idx4 / 102;
        int r    = idx4 - icl * 102;
        int row  = r / 17;
        int c4   = r - row * 17;
        i_icl[s] = icl;
        i_off[s] = (h0 + row) * IPITCH + c4 * 4;
    }

    unsigned long long acc2[4][8];
#pragma unroll
    for (int p = 0; p < 4; p++)
#pragma unroll
        for (int j = 0; j < 8; j++) acc2[p][j] = 0ull;

    auto issue_chunk = [&](int kc, int bu) {
        const unsigned sWu  = sW_u[bu];
        const unsigned sInu = sIn_u[bu];
        const float* ws = wbase + (size_t)kc * (NOCT * WNUM);
#pragma unroll
        for (int s = 0; s < 5; s++) {
            int idx4 = tid + s * 128;
            if (idx4 < WNUM / 4) {
                const float* g = ws + idx4 * 4;
                asm volatile("cp.async.cg.shared.global [%0], [%1], 16;"
                             :: "r"(sWu + (unsigned)(idx4 * 16)), "l"(g));
            }
        }
        const int ic0 = kc * ICC;
#pragma unroll
        for (int s = 0; s < 7; s++) {
            int idx4 = tid + s * 128;
            if (idx4 < INUM / 4) {
                const float* g = g_ipad +
                    ((size_t)(b * IC + ic0 + i_icl[s]) * 66) * IPITCH + i_off[s];
                asm volatile("cp.async.cg.shared.global [%0], [%1], 16;"
                             :: "r"(sInu + (unsigned)(idx4 * 16)), "l"(g));
            }
        }
        asm volatile("cp.async.commit_group;");
    };

    issue_chunk(0, 0);

    for (int kc = 0; kc < NCHUNK; kc++) {
        const int cur = kc & 1;
        if (kc < NCHUNK - 1) {
            issue_chunk(kc + 1, cur ^ 1);
            asm volatile("cp.async.wait_group 1;");
        } else {
            asm volatile("cp.async.wait_group 0;");
        }
        __syncthreads();

        const float* W_ = sW[cur];
        const float* I_ = sIn[cur];

#pragma unroll 1
        for (int ic = 0; ic < ICC; ic++) {
            const float* irow = I_ + (ic * 6 + tz) * IPITCH + tw0;
            const float* wrow = W_ + ic * 9 * OCT + to0;
#pragma unroll
            for (int kh = 0; kh < 3; kh++) {
                float4 f0 = *(const float4*)(irow + kh * IPITCH);
                float4 f1 = *(const float4*)(irow + kh * IPITCH + 4);
                float4 f2 = *(const float4*)(irow + kh * IPITCH + 8);
                unsigned long long ib[10];
                ib[0] = bc2(f0.x); ib[1] = bc2(f0.y); ib[2] = bc2(f0.z); ib[3] = bc2(f0.w);
                ib[4] = bc2(f1.x); ib[5] = bc2(f1.y); ib[6] = bc2(f1.z); ib[7] = bc2(f1.w);
                ib[8] = bc2(f2.x); ib[9] = bc2(f2.y);
#pragma unroll
                for (int kw = 0; kw < 3; kw++) {
                    const ulonglong2* wp =
                        (const ulonglong2*)(wrow + (kh * 3 + kw) * OCT);
                    ulonglong2 wa = wp[0];
                    ulonglong2 wb = wp[1];
#pragma unroll
                    for (int j = 0; j < 8; j++) {
                        FMA2(acc2[0][j], wa.x, ib[j + kw], acc2[0][j]);
                        FMA2(acc2[1][j], wa.y, ib[j + kw], acc2[1][j]);
                        FMA2(acc2[2][j], wb.x, ib[j + kw], acc2[2][j]);
                        FMA2(acc2[3][j], wb.y, ib[j + kw], acc2[3][j]);
                    }
                }
            }
        }
        __syncthreads();
    }

    const int h = h0 + tz;
#pragma unroll
    for (int p = 0; p < 4; p++) {
#pragma unroll
        for (int s = 0; s < 2; s++) {
            int oc = oc0 + to0 + 2 * p + s;
            float bias = bc[oc];
            float* op = &g_x[((size_t)(b * OC + oc) * HH + h) * WWW + tw0];
#pragma unroll
            for (int j = 0; j < 8; j++) {
                float v = (s == 0 ? lo32(acc2[p][j]) : hi32(acc2[p][j])) + bias;
                op[j] = v > 0.f ? v : 0.f;
            }
        }
    }
}

// ============ Kernel 2: heads (round-3 validated 64-thread version) ===========
__global__ __launch_bounds__(64) void heads_kernel(
    const float* __restrict__ meta,
    const float* __restrict__ Wcls, const float* __restrict__ bcls,
    const float* __restrict__ Wbb,  const float* __restrict__ bbb)
{
    __shared__ float sw[512 * 20];
    __shared__ float sb[20];

    const int h = blockIdx.x, b = blockIdx.y, tid = threadIdx.x;

    for (int idx = tid; idx < 512 * 20; idx += 64) {
        int c = idx / 20, o = idx - c * 20;
        sw[idx] = (o < 4) ? Wcls[o * 512 + c] : Wbb[(o - 4) * 512 + c];
    }
    if (tid < 20) sb[tid] = (tid < 4) ? bcls[tid] : bbb[tid - 4];
    __syncthreads();

    const int w = tid;
    float acc[20];
#pragma unroll
    for (int o = 0; o < 20; o++) acc[o] = 0.f;

    const float* xp = g_x + ((size_t)(b * OC) * HH + h) * WWW + w;
    for (int c = 0; c < 512; c++) {
        float xv = xp[(size_t)c * HH * WWW];
        const float4* wp = reinterpret_cast<const float4*>(&sw[c * 20]);
        float4 w0 = wp[0], w1 = wp[1], w2 = wp[2], w3 = wp[3], w4 = wp[4];
        acc[0]  = fmaf(xv, w0.x, acc[0]);  acc[1]  = fmaf(xv, w0.y, acc[1]);
        acc[2]  = fmaf(xv, w0.z, acc[2]);  acc[3]  = fmaf(xv, w0.w, acc[3]);
        acc[4]  = fmaf(xv, w1.x, acc[4]);  acc[5]  = fmaf(xv, w1.y, acc[5]);
        acc[6]  = fmaf(xv, w1.z, acc[6]);  acc[7]  = fmaf(xv, w1.w, acc[7]);
        acc[8]  = fmaf(xv, w2.x, acc[8]);  acc[9]  = fmaf(xv, w2.y, acc[9]);
        acc[10] = fmaf(xv, w2.z, acc[10]); acc[11] = fmaf(xv, w2.w, acc[11]);
        acc[12] = fmaf(xv, w3.x, acc[12]); acc[13] = fmaf(xv, w3.y, acc[13]);
        acc[14] = fmaf(xv, w3.z, acc[14]); acc[15] = fmaf(xv, w3.w, acc[15]);
        acc[16] = fmaf(xv, w4.x, acc[16]); acc[17] = fmaf(xv, w4.y, acc[17]);
        acc[18] = fmaf(xv, w4.z, acc[18]); acc[19] = fmaf(xv, w4.w, acc[19]);
    }

    float s[4];
#pragma unroll
    for (int a = 0; a < 4; a++) s[a] = acc[a] + sb[a];
    float prob[4];
#pragma unroll
    for (int a = 0; a < 4; a++) {
        int p = a ^ 2;
        float m  = fmaxf(s[a], s[p]);
        float ea = expf(s[a] - m);
        float eb = expf(s[p] - m);
        prob[a]  = ea / (ea + eb);
    }

    const float im_h = meta[b * 3 + 0];
    const float im_w = meta[b * 3 + 1];
    const float scl  = meta[b * 3 + 2];
    const float minsz = 16.f * scl;

    const int base = b * NA + (h * 64 + w) * 4;
#pragma unroll
    for (int a = 0; a < 4; a++) {
        float wa = (float)(64 << a);
        float cx = w * 16.f + 8.f;
        float cy = h * 16.f + 8.f;
        float d0 = acc[4 + a * 4 + 0] + sb[4 + a * 4 + 0];
        float d1 = acc[4 + a * 4 + 1] + sb[4 + a * 4 + 1];
        float d2 = acc[4 + a * 4 + 2] + sb[4 + a * 4 + 2];
        float d3 = acc[4 + a * 4 + 3] + sb[4 + a * 4 + 3];
        float pcx = d0 * wa + cx, pcy = d1 * wa + cy;
        float pw  = expf(d2) * wa, ph = expf(d3) * wa;
        float x1 = pcx - 0.5f * pw, y1 = pcy - 0.5f * ph;
        float x2 = pcx + 0.5f * pw, y2 = pcy + 0.5f * ph;
        x1 = fminf(fmaxf(x1, 0.f), im_w - 1.f);
        x2 = fminf(fmaxf(x2, 0.f), im_w - 1.f);
        y1 = fminf(fmaxf(y1, 0.f), im_h - 1.f);
        y2 = fminf(fmaxf(y2, 0.f), im_h - 1.f);
        bool keep = (x2 - x1 + 1.f >= minsz) && (y2 - y1 + 1.f >= minsz);
        g_scores[base + a] = keep ? prob[a] : -INFINITY;
        g_boxes[base + a]  = make_float4(x1, y1, x2, y2);
    }
}

// ================= Kernel 3: exact top-6000 mark (per image) ==================
__global__ __launch_bounds__(1024) void topk_kernel()
{
    const int b   = blockIdx.x;
    const int tid = threadIdx.x;
    float* scores = g_scores + b * NA;

    unsigned key[16];
    const int i0 = tid * 16;
#pragma unroll
    for (int i = 0; i < 16; i++) key[i] = ordkey(scores[i0 + i]);

    __shared__ int wsum[32];
    __shared__ int s_total;
    const int lane = tid & 31, wid = tid >> 5;

    auto count_ge = [&](unsigned cand) -> int {
        int local = 0;
#pragma unroll
        for (int i = 0; i < 16; i++) local += (key[i] >= cand) ? 1 : 0;
        for (int off = 16; off; off >>= 1)
            local += __shfl_down_sync(0xFFFFFFFFu, local, off);
        if (lane == 0) wsum[wid] = local;
        __syncthreads();
        if (tid == 0) {
            int st = 0;
            for (int k = 0; k < 32; k++) st += wsum[k];
            s_total = st;
        }
        __syncthreads();
        int r = s_total;
        __syncthreads();
        return r;
    };

    unsigned thr = 0;
    for (int bit = 31; bit >= 0; bit--) {
        unsigned cand = thr | (1u << bit);
        if (count_ge(cand) >= PRE_NMS_K) thr = cand;
    }
    const int n_gt = count_ge(thr + 1u);
    const int need = PRE_NMS_K - n_gt;

    int my_eq = 0;
#pragma unroll
    for (int i = 0; i < 16; i++) my_eq += (key[i] == thr) ? 1 : 0;

    int v = my_eq;
    for (int off = 1; off < 32; off <<= 1) {
        int tt = __shfl_up_sync(0xFFFFFFFFu, v, off);
        if (lane >= off) v += tt;
    }
    __syncthreads();
    if (lane == 31) wsum[wid] = v;
    __syncthreads();
    if (wid == 0) {
        int sv = wsum[lane];
        for (int off = 1; off < 32; off <<= 1) {
            int tt = __shfl_up_sync(0xFFFFFFFFu, sv, off);
            if (lane >= off) sv += tt;
        }
        wsum[lane] = sv;
    }
    __syncthreads();
    int rank = v - my_eq + (wid ? wsum[wid - 1] : 0);

#pragma unroll
    for (int i = 0; i < 16; i++) {
        if (key[i] == thr) {
            if (rank >= need) scores[i0 + i] = -INFINITY;
            rank++;
        } else if (key[i] < thr) {
            scores[i0 + i] = -INFINITY;
        }
    }
}

// ===================== Kernel 4: exact greedy NMS (per image) =================
__global__ __launch_bounds__(512) void nms_kernel(float* __restrict__ out)
{
    const int b   = blockIdx.x;
    const int tid = threadIdx.x;
    const float4* boxes = g_boxes + b * NA;

    float sc[32];
    const int i0 = tid * 32;
#pragma unroll
    for (int i = 0; i < 32; i++) sc[i] = g_scores[b * NA + i0 + i];

    __shared__ unsigned long long swm[16];
    __shared__ unsigned long long s_best;
    __shared__ float4 s_box;
    __shared__ float  s_area;
    __shared__ int    s_firstj;

    const int lane = tid & 31, wid = tid >> 5;

    for (int it = 0; it < POST_NMS_K; it++) {
        unsigned long long loc = ((unsigned long long)ORD_NEG_INF << 32);
#pragma unroll
        for (int i = 0; i < 32; i++) {
            unsigned long long kk =
                ((unsigned long long)ordkey(sc[i]) << 32) |
                (unsigned)(65535 - (i0 + i));
            loc = (kk > loc) ? kk : loc;
        }
        for (int off = 16; off; off >>= 1) {
            unsigned long long o = __shfl_down_sync(0xFFFFFFFFu, loc, off);
            loc = (o > loc) ? o : loc;
        }
        if (lane == 0) swm[wid] = loc;
        __syncthreads();
        if (tid < 16) {
            unsigned long long vv = swm[tid];
            for (int off = 8; off; off >>= 1) {
                unsigned long long o = __shfl_down_sync(0x0000FFFFu, vv, off);
                vv = (o > vv) ? o : vv;
            }
            if (tid == 0) s_best = vv;
        }
        __syncthreads();

        if (tid == 0) {
            unsigned long long best = s_best;
            unsigned keypart = (unsigned)(best >> 32);
            int j;
            if (keypart == ORD_NEG_INF && it > 0) j = s_firstj;
            else j = 65535 - (int)(best & 0xFFFFFFFFull);
            if (it == 0) s_firstj = j;
            float4 bx = boxes[j];
            s_box  = bx;
            s_area = (bx.z - bx.x + 1.f) * (bx.w - bx.y + 1.f);
            float* o = out + (size_t)(b * POST_NMS_K + it) * 5;
            o[0] = (float)b; o[1] = bx.x; o[2] = bx.y; o[3] = bx.z; o[4] = bx.w;
        }
        __syncthreads();

        const float4 jb = s_box;
        const float  ja = s_area;
#pragma unroll 4
        for (int i = 0; i < 32; i++) {
            float4 bb = boxes[i0 + i];
            float xx1 = fmaxf(jb.x, bb.x);
            float yy1 = fmaxf(jb.y, bb.y);
            float xx2 = fminf(jb.z, bb.z);
            float yy2 = fminf(jb.w, bb.w);
            float iw  = fmaxf(xx2 - xx1 + 1.f, 0.f);
            float ih  = fmaxf(yy2 - yy1 + 1.f, 0.f);
            float inter = iw * ih;
            float area  = (bb.z - bb.x + 1.f) * (bb.w - bb.y + 1.f);
            float iou   = inter / (ja + area - inter);
            if (iou > 0.7f) sc[i] = -INFINITY;
        }
    }
}

// ================================ launcher ====================================
extern "C" void kernel_launch(void* const* d_in, const int* in_sizes, int n_in,
                              void* d_out, int out_size)
{
    const float* feat = (const float*)d_in[0];
    const float* meta = (const float*)d_in[1];
    const float* Wc   = (const float*)d_in[3];
    const float* bc   = (const float*)d_in[4];
    const float* Wcls = (const float*)d_in[5];
    const float* bcls = (const float*)d_in[6];
    const float* Wbb  = (const float*)d_in[7];
    const float* bbb  = (const float*)d_in[8];
    float* out = (float*)d_out;

    cudaFuncSetAttribute(conv_mma_kernel,
                         cudaFuncAttributeMaxDynamicSharedMemorySize, CONV_SMEM);

    zero_flag_kernel<<<1, 1>>>();
    // --- mma path: 8-bit exact chunks + accumulator drains ---
    prep_w_tc<<<(4 * NKK8 * 1024 + 255) / 256, 256>>>(Wc);
    prep_x_tc<<<(NB * 66 * 66 * 1024 + 255) / 256, 256>>>(feat);
    conv_mma_kernel<<<dim3(4, 32, 2), 256, CONV_SMEM>>>(bc);
    // --- verify samples (threshold 2e-4: structural vs rounding) ---
    check_kernel<<<dim3(512, 2), 128>>>(feat, Wc, bc);
    // --- validated fallback path (runs only if flag set) ---
    prep_weights<<<(NCHUNK * NOCT * WNUM + 255) / 256, 256>>>(Wc);
    prep_input<<<(NB * IC * 66 * IPITCH + 255) / 256, 256>>>(feat);
    conv_ffma2_kernel<<<dim3(16, 16, 2), 128>>>(bc);
    // --- validated tail (64-thread heads) ---
    heads_kernel<<<dim3(64, 2), 64>>>(meta, Wcls, bcls, Wbb, bbb);
    topk_kernel<<<2, 1024>>>();
    nms_kernel<<<2, 512>>>(out);
}

// round 15
// speedup vs baseline: 1.7946x; 1.0444x over previous
#include <cuda_runtime.h>
#include <stdint.h>
#include <math.h>

#define IC 1024
#define OC 512
#define HH 64
#define WWW 64
#define NB 2
#define NA 16384
#define PRE_NMS_K 6000
#define POST_NMS_K 300

// ---- mma conv params ----
#define NKK8 1152                 // K/8 = 9216/8 (tap-major: t*1024+ic)
#define NITER 288                 // K stages of 32 (9 taps x 32 ic-chunks)
#define STAGE_BYTES 104448        // A 49152 + B 55296
#define B_OFF 49152
#define CONV_SMEM (2 * STAGE_BYTES)   // 208896

// ---------------- scratch (static device allocations, allowed) ----------------
__device__ float g_x[NB * OC * HH * WWW];
__device__ float g_wtc[4 * NKK8 * 3 * 8 * 32 * 4];
__device__ float g_xs3[NB * 66 * 66 * 3 * 1024];
__device__ float g_scores[NB * NA];
__device__ float4 g_boxes[NB * NA];

__device__ __forceinline__ unsigned ordkey(float f) {
    unsigned u = __float_as_uint(f);
    return (u & 0x80000000u) ? ~u : (u | 0x80000000u);
}
#define ORD_NEG_INF 0x007FFFFFu

// 8-significand-bit chunks (bf16-exact). Exact 3-term decomposition; each
// chunk survives any HW input truncation >= 8 bits.
__device__ __forceinline__ float chunk8(float v) {
    return __uint_as_float(__float_as_uint(v) & 0xFFFF0000u);
}

#define MMA_TF32(c, a, b) \
    asm volatile("mma.sync.aligned.m16n8k8.row.col.f32.tf32.tf32.f32 " \
        "{%0,%1,%2,%3}, {%4,%5,%6,%7}, {%8,%9}, {%0,%1,%2,%3};" \
        : "+f"((c)[0]), "+f"((c)[1]), "+f"((c)[2]), "+f"((c)[3]) \
        : "r"((a).x), "r"((a).y), "r"((a).z), "r"((a).w), \
          "r"((b)[0]), "r"((b)[1]))

// ======================= mma path pre-passes ==================================
// A-fragment per PTX ISA m16n8k8.tf32:
//   r0:(m,k) r1:(m+8,k) r2:(m,k+4) r3:(m+8,k+4); m=lam>>2, k=lam&3
__global__ __launch_bounds__(256) void prep_w_tc(const float* __restrict__ Wc)
{
    int idx = blockIdx.x * 256 + threadIdx.x;
    if (idx >= 4 * NKK8 * 8 * 32 * 4) return;
    int r   = idx & 3;
    int lam = (idx >> 2) & 31;
    int mf  = (idx >> 7) & 7;
    int rest = idx >> 10;
    int kk8 = rest % NKK8;
    int mt  = rest / NKK8;
    int oc = mt * 128 + mf * 16 + (lam >> 2) + (r & 1) * 8;
    int t  = kk8 / 128;
    int ic = (kk8 % 128) * 8 + (lam & 3) + (r >> 1) * 4;
    float v  = Wc[((size_t)oc * IC + ic) * 9 + t];
    float a0 = chunk8(v);
    float r1 = v - a0;
    float a1 = chunk8(r1);
    float a2 = r1 - a1;
    size_t base = (size_t)(mt * NKK8 + kk8) * 3072 + mf * 128 + lam * 4 + r;
    g_wtc[base]        = a0;
    g_wtc[base + 1024] = a1;
    g_wtc[base + 2048] = a2;
}

__global__ __launch_bounds__(256) void prep_x_tc(const float* __restrict__ in)
{
    int idx = blockIdx.x * 256 + threadIdx.x;
    if (idx >= NB * 66 * 66 * 1024) return;
    int ic = idx & 1023;
    int pix = idx >> 10;
    int pc = pix % 66;
    int rest2 = pix / 66;
    int pr = rest2 % 66;
    int b  = rest2 / 66;
    int h = pr - 1, w = pc - 1;
    float v = 0.f;
    if (h >= 0 && h < HH && w >= 0 && w < WWW)
        v = in[(((size_t)b * IC + ic) * HH + h) * WWW + w];
    float a0 = chunk8(v);
    float r1 = v - a0;
    float a1 = chunk8(r1);
    float a2 = r1 - a1;
    size_t base = (size_t)pix * 3072 + ic;
    g_xs3[base]        = a0;
    g_xs3[base + 1024] = a1;
    g_xs3[base + 2048] = a2;
}

// ===== mma conv: 8-bit chunks + accumulator drains (anti truncation-bias) =====
__global__ __launch_bounds__(256, 1) void conv_mma_kernel(const float* __restrict__ bc)
{
    extern __shared__ char smem[];
    const int tid  = threadIdx.x;
    const int wid  = tid >> 5;
    const int lane = tid & 31;
    const int mt = blockIdx.x;
    const int nt = blockIdx.y;
    const int b  = blockIdx.z;
    const int h0 = nt * 2;
    const int wm = wid & 1;
    const int wn = wid >> 1;

    float acc[4][4][4];     // in-MMA accumulator (short chains)
    float accR[4][4][4];    // RN-drained master accumulator
#pragma unroll
    for (int i = 0; i < 4; i++)
#pragma unroll
        for (int j = 0; j < 4; j++)
#pragma unroll
            for (int r = 0; r < 4; r++) { acc[i][j][r] = 0.f; accR[i][j][r] = 0.f; }

    const char*  wsrc = (const char*)(g_wtc + (size_t)mt * NKK8 * 3072);
    const float* xb   = g_xs3 + (size_t)b * 66 * 66 * 3072;

    int bl_n[12], bl_u[12], bl_s[12];
#pragma unroll
    for (int j = 0; j < 12; j++) {
        int id = tid + j * 256;
        bl_s[j] = id >> 10;
        bl_n[j] = (id >> 3) & 127;
        bl_u[j] = id & 7;
    }

    auto issue = [&](int i, int st) {
        char* sa = smem + st * STAGE_BYTES;
        const char* asrc = wsrc + (size_t)i * 49152;
        unsigned au = (unsigned)__cvta_generic_to_shared(sa);
#pragma unroll
        for (int j = 0; j < 12; j++) {
            int off = (tid + j * 256) * 16;
            asm volatile("cp.async.cg.shared.global [%0], [%1], 16;"
                         :: "r"(au + off), "l"(asrc + off));
        }
        int t = i >> 5, c32 = i & 31;
        int kh = t / 3, kw = t - kh * 3;
        unsigned bu = au + B_OFF;
#pragma unroll
        for (int j = 0; j < 12; j++) {
            int n = bl_n[j];
            int pr = h0 + (n >> 6) + kh;
            int pc = (n & 63) + kw;
            const float* src = xb + (size_t)(pr * 66 + pc) * 3072 + (bl_s[j] << 10)
                                  + (c32 << 5) + (bl_u[j] << 2);
            unsigned dst = bu + bl_s[j] * 18432 + n * 144 + bl_u[j] * 16;
            asm volatile("cp.async.cg.shared.global [%0], [%1], 16;"
                         :: "r"(dst), "l"(src));
        }
        asm volatile("cp.async.commit_group;");
    };

    issue(0, 0);

    for (int i = 0; i < NITER; i++) {
        const int st = i & 1;
        if (i + 1 < NITER) {
            issue(i + 1, st ^ 1);
            asm volatile("cp.async.wait_group 1;");
        } else {
            asm volatile("cp.async.wait_group 0;");
        }
        __syncthreads();

        const char* sa = smem + st * STAGE_BYTES;
#pragma unroll
        for (int kk8 = 0; kk8 < 4; kk8++) {
            uint32_t bb[3][4][2];
#pragma unroll
            for (int s = 0; s < 3; s++)
#pragma unroll
                for (int nf = 0; nf < 4; nf++) {
                    const char* ba = sa + B_OFF + s * 18432
                        + (wn * 32 + nf * 8 + (lane >> 2)) * 144
                        + (kk8 * 8 + (lane & 3)) * 4;
                    bb[s][nf][0] = *(const uint32_t*)ba;
                    bb[s][nf][1] = *(const uint32_t*)(ba + 16);
                }
            // s grouped to cap live A registers (16 at a time)
            {
                uint4 a[4];
#pragma unroll
                for (int mf = 0; mf < 4; mf++)
                    a[mf] = *(const uint4*)(sa +
                        (((kk8 * 3 + 0) * 8 + (wm * 4 + mf)) * 512) + lane * 16);
#pragma unroll
                for (int mf = 0; mf < 4; mf++)
#pragma unroll
                    for (int nf = 0; nf < 4; nf++) {
                        MMA_TF32(acc[mf][nf], a[mf], bb[0][nf]);
                        MMA_TF32(acc[mf][nf], a[mf], bb[1][nf]);
                        MMA_TF32(acc[mf][nf], a[mf], bb[2][nf]);
                    }
            }
            {
                uint4 a[4];
#pragma unroll
                for (int mf = 0; mf < 4; mf++)
                    a[mf] = *(const uint4*)(sa +
                        (((kk8 * 3 + 1) * 8 + (wm * 4 + mf)) * 512) + lane * 16);
#pragma unroll
                for (int mf = 0; mf < 4; mf++)
#pragma unroll
                    for (int nf = 0; nf < 4; nf++) {
                        MMA_TF32(acc[mf][nf], a[mf], bb[0][nf]);
                        MMA_TF32(acc[mf][nf], a[mf], bb[1][nf]);
                    }
            }
            {
                uint4 a[4];
#pragma unroll
                for (int mf = 0; mf < 4; mf++)
                    a[mf] = *(const uint4*)(sa +
                        (((kk8 * 3 + 2) * 8 + (wm * 4 + mf)) * 512) + lane * 16);
#pragma unroll
                for (int mf = 0; mf < 4; mf++)
#pragma unroll
                    for (int nf = 0; nf < 4; nf++)
                        MMA_TF32(acc[mf][nf], a[mf], bb[0][nf]);
            }
        }
        __syncthreads();

        // drain: every 16 iterations, fold short MMA chain into RN accumulator
        if ((i & 15) == 15) {
#pragma unroll
            for (int mf = 0; mf < 4; mf++)
#pragma unroll
                for (int nf = 0; nf < 4; nf++)
#pragma unroll
                    for (int r = 0; r < 4; r++) {
                        accR[mf][nf][r] += acc[mf][nf][r];
                        acc[mf][nf][r] = 0.f;
                    }
        }
    }

#pragma unroll
    for (int mf = 0; mf < 4; mf++) {
        int oc0 = mt * 128 + wm * 64 + mf * 16 + (lane >> 2);
        float bias0 = bc[oc0];
        float bias8 = bc[oc0 + 8];
#pragma unroll
        for (int nf = 0; nf < 4; nf++) {
            int nl = wn * 32 + nf * 8 + (lane & 3) * 2;
            int h = h0 + (nl >> 6);
            int w = nl & 63;
            float2 v0, v1;
            v0.x = fmaxf(accR[mf][nf][0] + acc[mf][nf][0] + bias0, 0.f);
            v0.y = fmaxf(accR[mf][nf][1] + acc[mf][nf][1] + bias0, 0.f);
            v1.x = fmaxf(accR[mf][nf][2] + acc[mf][nf][2] + bias8, 0.f);
            v1.y = fmaxf(accR[mf][nf][3] + acc[mf][nf][3] + bias8, 0.f);
            *(float2*)(g_x + (((size_t)(b * OC + oc0) * HH + h) * WWW + w))     = v0;
            *(float2*)(g_x + (((size_t)(b * OC + oc0 + 8) * HH + h) * WWW + w)) = v1;
        }
    }
}

// ============ Kernel 2: heads (round-3 validated 64-thread version) ===========
__global__ __launch_bounds__(64) void heads_kernel(
    const float* __restrict__ meta,
    const float* __restrict__ Wcls, const float* __restrict__ bcls,
    const float* __restrict__ Wbb,  const float* __restrict__ bbb)
{
    __shared__ float sw[512 * 20];
    __shared__ float sb[20];

    const int h = blockIdx.x, b = blockIdx.y, tid = threadIdx.x;

    for (int idx = tid; idx < 512 * 20; idx += 64) {
        int c = idx / 20, o = idx - c * 20;
        sw[idx] = (o < 4) ? Wcls[o * 512 + c] : Wbb[(o - 4) * 512 + c];
    }
    if (tid < 20) sb[tid] = (tid < 4) ? bcls[tid] : bbb[tid - 4];
    __syncthreads();

    const int w = tid;
    float acc[20];
#pragma unroll
    for (int o = 0; o < 20; o++) acc[o] = 0.f;

    const float* xp = g_x + ((size_t)(b * OC) * HH + h) * WWW + w;
    for (int c = 0; c < 512; c++) {
        float xv = xp[(size_t)c * HH * WWW];
        const float4* wp = reinterpret_cast<const float4*>(&sw[c * 20]);
        float4 w0 = wp[0], w1 = wp[1], w2 = wp[2], w3 = wp[3], w4 = wp[4];
        acc[0]  = fmaf(xv, w0.x, acc[0]);  acc[1]  = fmaf(xv, w0.y, acc[1]);
        acc[2]  = fmaf(xv, w0.z, acc[2]);  acc[3]  = fmaf(xv, w0.w, acc[3]);
        acc[4]  = fmaf(xv, w1.x, acc[4]);  acc[5]  = fmaf(xv, w1.y, acc[5]);
        acc[6]  = fmaf(xv, w1.z, acc[6]);  acc[7]  = fmaf(xv, w1.w, acc[7]);
        acc[8]  = fmaf(xv, w2.x, acc[8]);  acc[9]  = fmaf(xv, w2.y, acc[9]);
        acc[10] = fmaf(xv, w2.z, acc[10]); acc[11] = fmaf(xv, w2.w, acc[11]);
        acc[12] = fmaf(xv, w3.x, acc[12]); acc[13] = fmaf(xv, w3.y, acc[13]);
        acc[14] = fmaf(xv, w3.z, acc[14]); acc[15] = fmaf(xv, w3.w, acc[15]);
        acc[16] = fmaf(xv, w4.x, acc[16]); acc[17] = fmaf(xv, w4.y, acc[17]);
        acc[18] = fmaf(xv, w4.z, acc[18]); acc[19] = fmaf(xv, w4.w, acc[19]);
    }

    float s[4];
#pragma unroll
    for (int a = 0; a < 4; a++) s[a] = acc[a] + sb[a];
    float prob[4];
#pragma unroll
    for (int a = 0; a < 4; a++) {
        int p = a ^ 2;
        float m  = fmaxf(s[a], s[p]);
        float ea = expf(s[a] - m);
        float eb = expf(s[p] - m);
        prob[a]  = ea / (ea + eb);
    }

    const float im_h = meta[b * 3 + 0];
    const float im_w = meta[b * 3 + 1];
    const float scl  = meta[b * 3 + 2];
    const float minsz = 16.f * scl;

    const int base = b * NA + (h * 64 + w) * 4;
#pragma unroll
    for (int a = 0; a < 4; a++) {
        float wa = (float)(64 << a);
        float cx = w * 16.f + 8.f;
        float cy = h * 16.f + 8.f;
        float d0 = acc[4 + a * 4 + 0] + sb[4 + a * 4 + 0];
        float d1 = acc[4 + a * 4 + 1] + sb[4 + a * 4 + 1];
        float d2 = acc[4 + a * 4 + 2] + sb[4 + a * 4 + 2];
        float d3 = acc[4 + a * 4 + 3] + sb[4 + a * 4 + 3];
        float pcx = d0 * wa + cx, pcy = d1 * wa + cy;
        float pw  = expf(d2) * wa, ph = expf(d3) * wa;
        float x1 = pcx - 0.5f * pw, y1 = pcy - 0.5f * ph;
        float x2 = pcx + 0.5f * pw, y2 = pcy + 0.5f * ph;
        x1 = fminf(fmaxf(x1, 0.f), im_w - 1.f);
        x2 = fminf(fmaxf(x2, 0.f), im_w - 1.f);
        y1 = fminf(fmaxf(y1, 0.f), im_h - 1.f);
        y2 = fminf(fmaxf(y2, 0.f), im_h - 1.f);
        bool keep = (x2 - x1 + 1.f >= minsz) && (y2 - y1 + 1.f >= minsz);
        g_scores[base + a] = keep ? prob[a] : -INFINITY;
        g_boxes[base + a]  = make_float4(x1, y1, x2, y2);
    }
}

// ================= Kernel 3: exact top-6000 mark (per image) ==================
__global__ __launch_bounds__(1024) void topk_kernel()
{
    const int b   = blockIdx.x;
    const int tid = threadIdx.x;
    float* scores = g_scores + b * NA;

    unsigned key[16];
    const int i0 = tid * 16;
#pragma unroll
    for (int i = 0; i < 16; i++) key[i] = ordkey(scores[i0 + i]);

    __shared__ int wsum[32];
    __shared__ int s_total;
    const int lane = tid & 31, wid = tid >> 5;

    auto count_ge = [&](unsigned cand) -> int {
        int local = 0;
#pragma unroll
        for (int i = 0; i < 16; i++) local += (key[i] >= cand) ? 1 : 0;
        for (int off = 16; off; off >>= 1)
            local += __shfl_down_sync(0xFFFFFFFFu, local, off);
        if (lane == 0) wsum[wid] = local;
        __syncthreads();
        if (tid == 0) {
            int st = 0;
            for (int k = 0; k < 32; k++) st += wsum[k];
            s_total = st;
        }
        __syncthreads();
        int r = s_total;
        __syncthreads();
        return r;
    };

    unsigned thr = 0;
    for (int bit = 31; bit >= 0; bit--) {
        unsigned cand = thr | (1u << bit);
        if (count_ge(cand) >= PRE_NMS_K) thr = cand;
    }
    const int n_gt = count_ge(thr + 1u);
    const int need = PRE_NMS_K - n_gt;

    int my_eq = 0;
#pragma unroll
    for (int i = 0; i < 16; i++) my_eq += (key[i] == thr) ? 1 : 0;

    int v = my_eq;
    for (int off = 1; off < 32; off <<= 1) {
        int tt = __shfl_up_sync(0xFFFFFFFFu, v, off);
        if (lane >= off) v += tt;
    }
    __syncthreads();
    if (lane == 31) wsum[wid] = v;
    __syncthreads();
    if (wid == 0) {
        int sv = wsum[lane];
        for (int off = 1; off < 32; off <<= 1) {
            int tt = __shfl_up_sync(0xFFFFFFFFu, sv, off);
            if (lane >= off) sv += tt;
        }
        wsum[lane] = sv;
    }
    __syncthreads();
    int rank = v - my_eq + (wid ? wsum[wid - 1] : 0);

#pragma unroll
    for (int i = 0; i < 16; i++) {
        if (key[i] == thr) {
            if (rank >= need) scores[i0 + i] = -INFINITY;
            rank++;
        } else if (key[i] < thr) {
            scores[i0 + i] = -INFINITY;
        }
    }
}

// ===================== Kernel 4: exact greedy NMS (per image) =================
__global__ __launch_bounds__(512) void nms_kernel(float* __restrict__ out)
{
    const int b   = blockIdx.x;
    const int tid = threadIdx.x;
    const float4* boxes = g_boxes + b * NA;

    float sc[32];
    const int i0 = tid * 32;
#pragma unroll
    for (int i = 0; i < 32; i++) sc[i] = g_scores[b * NA + i0 + i];

    __shared__ unsigned long long swm[16];
    __shared__ unsigned long long s_best;
    __shared__ float4 s_box;
    __shared__ float  s_area;
    __shared__ int    s_firstj;

    const int lane = tid & 31, wid = tid >> 5;

    for (int it = 0; it < POST_NMS_K; it++) {
        unsigned long long loc = ((unsigned long long)ORD_NEG_INF << 32);
#pragma unroll
        for (int i = 0; i < 32; i++) {
            unsigned long long kk =
                ((unsigned long long)ordkey(sc[i]) << 32) |
                (unsigned)(65535 - (i0 + i));
            loc = (kk > loc) ? kk : loc;
        }
        for (int off = 16; off; off >>= 1) {
            unsigned long long o = __shfl_down_sync(0xFFFFFFFFu, loc, off);
            loc = (o > loc) ? o : loc;
        }
        if (lane == 0) swm[wid] = loc;
        __syncthreads();
        if (tid < 16) {
            unsigned long long vv = swm[tid];
            for (int off = 8; off; off >>= 1) {
                unsigned long long o = __shfl_down_sync(0x0000FFFFu, vv, off);
                vv = (o > vv) ? o : vv;
            }
            if (tid == 0) s_best = vv;
        }
        __syncthreads();

        if (tid == 0) {
            unsigned long long best = s_best;
            unsigned keypart = (unsigned)(best >> 32);
            int j;
            if (keypart == ORD_NEG_INF && it > 0) j = s_firstj;
            else j = 65535 - (int)(best & 0xFFFFFFFFull);
            if (it == 0) s_firstj = j;
            float4 bx = boxes[j];
            s_box  = bx;
            s_area = (bx.z - bx.x + 1.f) * (bx.w - bx.y + 1.f);
            float* o = out + (size_t)(b * POST_NMS_K + it) * 5;
            o[0] = (float)b; o[1] = bx.x; o[2] = bx.y; o[3] = bx.z; o[4] = bx.w;
        }
        __syncthreads();

        const float4 jb = s_box;
        const float  ja = s_area;
#pragma unroll 4
        for (int i = 0; i < 32; i++) {
            float4 bb = boxes[i0 + i];
            float xx1 = fmaxf(jb.x, bb.x);
            float yy1 = fmaxf(jb.y, bb.y);
            float xx2 = fminf(jb.z, bb.z);
            float yy2 = fminf(jb.w, bb.w);
            float iw  = fmaxf(xx2 - xx1 + 1.f, 0.f);
            float ih  = fmaxf(yy2 - yy1 + 1.f, 0.f);
            float inter = iw * ih;
            float area  = (bb.z - bb.x + 1.f) * (bb.w - bb.y + 1.f);
            float iou   = inter / (ja + area - inter);
            if (iou > 0.7f) sc[i] = -INFINITY;
        }
    }
}

// ================================ launcher ====================================
extern "C" void kernel_launch(void* const* d_in, const int* in_sizes, int n_in,
                              void* d_out, int out_size)
{
    const float* feat = (const float*)d_in[0];
    const float* meta = (const float*)d_in[1];
    // d_in[2] = gt_boxes (unused by the reference output)
    const float* Wc   = (const float*)d_in[3];
    const float* bc   = (const float*)d_in[4];
    const float* Wcls = (const float*)d_in[5];
    const float* bcls = (const float*)d_in[6];
    const float* Wbb  = (const float*)d_in[7];
    const float* bbb  = (const float*)d_in[8];
    float* out = (float*)d_out;

    cudaFuncSetAttribute(conv_mma_kernel,
                         cudaFuncAttributeMaxDynamicSharedMemorySize, CONV_SMEM);

    prep_w_tc<<<(4 * NKK8 * 1024 + 255) / 256, 256>>>(Wc);
    prep_x_tc<<<(NB * 66 * 66 * 1024 + 255) / 256, 256>>>(feat);
    conv_mma_kernel<<<dim3(4, 32, 2), 256, CONV_SMEM>>>(bc);
    heads_kernel<<<dim3(64, 2), 64>>>(meta, Wcls, bcls, Wbb, bbb);
    topk_kernel<<<2, 1024>>>();
    nms_kernel<<<2, 512>>>(out);
}

// round 17
// speedup vs baseline: 2.9912x; 1.6667x over previous
#include <cuda_runtime.h>
#include <stdint.h>
#include <math.h>

#define IC 1024
#define OC 512
#define HH 64
#define WWW 64
#define NB 2
#define NA 16384
#define PRE_NMS_K 6000
#define POST_NMS_K 300
#define NSLOT 12                  // 512*12 = 6144 >= 6000
#define NPAD (512 * NSLOT)        // 6144 padded candidate slots

// ---- mma conv params ----
#define NKK8 1152
#define NITER 288
#define STAGE_BYTES 104448        // A 49152 + B 55296
#define B_OFF 49152
#define CONV_SMEM (2 * STAGE_BYTES)
#define NMS_SMEM (NPAD * 16)      // 98304 B (padded; reads are unguarded)

// ---------------- scratch (static device allocations, allowed) ----------------
__device__ float g_x[NB * OC * HH * WWW];
__device__ float g_wtc[4 * NKK8 * 3 * 8 * 32 * 4];
__device__ float g_xs3[NB * 66 * 66 * 3 * 1024];
__device__ float g_scores[NB * NA];
__device__ float4 g_boxes[NB * NA];
__device__ unsigned long long g_cand_key[NB * PRE_NMS_K];
__device__ float4 g_cand_box[NB * PRE_NMS_K];

__device__ __forceinline__ unsigned ordkey(float f) {
    unsigned u = __float_as_uint(f);
    return (u & 0x80000000u) ? ~u : (u | 0x80000000u);
}
#define ORD_NEG_INF 0x007FFFFFu

// 8-significand-bit chunks (bf16-exact), exact 3-term decomposition.
__device__ __forceinline__ float chunk8(float v) {
    return __uint_as_float(__float_as_uint(v) & 0xFFFF0000u);
}

#define MMA_TF32(c, a, b) \
    asm volatile("mma.sync.aligned.m16n8k8.row.col.f32.tf32.tf32.f32 " \
        "{%0,%1,%2,%3}, {%4,%5,%6,%7}, {%8,%9}, {%0,%1,%2,%3};" \
        : "+f"((c)[0]), "+f"((c)[1]), "+f"((c)[2]), "+f"((c)[3]) \
        : "r"((a).x), "r"((a).y), "r"((a).z), "r"((a).w), \
          "r"((b)[0]), "r"((b)[1]))

// ======================= mma path pre-passes ==================================
__global__ __launch_bounds__(256) void prep_w_tc(const float* __restrict__ Wc)
{
    int idx = blockIdx.x * 256 + threadIdx.x;
    if (idx >= 4 * NKK8 * 8 * 32 * 4) return;
    int r   = idx & 3;
    int lam = (idx >> 2) & 31;
    int mf  = (idx >> 7) & 7;
    int rest = idx >> 10;
    int kk8 = rest % NKK8;
    int mt  = rest / NKK8;
    int oc = mt * 128 + mf * 16 + (lam >> 2) + (r & 1) * 8;
    int t  = kk8 / 128;
    int ic = (kk8 % 128) * 8 + (lam & 3) + (r >> 1) * 4;
    float v  = Wc[((size_t)oc * IC + ic) * 9 + t];
    float a0 = chunk8(v);
    float r1 = v - a0;
    float a1 = chunk8(r1);
    float a2 = r1 - a1;
    size_t base = (size_t)(mt * NKK8 + kk8) * 3072 + mf * 128 + lam * 4 + r;
    g_wtc[base]        = a0;
    g_wtc[base + 1024] = a1;
    g_wtc[base + 2048] = a2;
}

__global__ __launch_bounds__(256) void prep_x_tc(const float* __restrict__ in)
{
    int idx = blockIdx.x * 256 + threadIdx.x;
    if (idx >= NB * 66 * 66 * 1024) return;
    int ic = idx & 1023;
    int pix = idx >> 10;
    int pc = pix % 66;
    int rest2 = pix / 66;
    int pr = rest2 % 66;
    int b  = rest2 / 66;
    int h = pr - 1, w = pc - 1;
    float v = 0.f;
    if (h >= 0 && h < HH && w >= 0 && w < WWW)
        v = in[(((size_t)b * IC + ic) * HH + h) * WWW + w];
    float a0 = chunk8(v);
    float r1 = v - a0;
    float a1 = chunk8(r1);
    float a2 = r1 - a1;
    size_t base = (size_t)pix * 3072 + ic;
    g_xs3[base]        = a0;
    g_xs3[base + 1024] = a1;
    g_xs3[base + 2048] = a2;
}

// ===== mma conv: 8-bit chunks + accumulator drains (validated round 14) ======
__global__ __launch_bounds__(256, 1) void conv_mma_kernel(const float* __restrict__ bc)
{
    extern __shared__ char smem[];
    const int tid  = threadIdx.x;
    const int wid  = tid >> 5;
    const int lane = tid & 31;
    const int mt = blockIdx.x;
    const int nt = blockIdx.y;
    const int b  = blockIdx.z;
    const int h0 = nt * 2;
    const int wm = wid & 1;
    const int wn = wid >> 1;

    float acc[4][4][4];
    float accR[4][4][4];
#pragma unroll
    for (int i = 0; i < 4; i++)
#pragma unroll
        for (int j = 0; j < 4; j++)
#pragma unroll
            for (int r = 0; r < 4; r++) { acc[i][j][r] = 0.f; accR[i][j][r] = 0.f; }

    const char*  wsrc = (const char*)(g_wtc + (size_t)mt * NKK8 * 3072);
    const float* xb   = g_xs3 + (size_t)b * 66 * 66 * 3072;

    int bl_n[12], bl_u[12], bl_s[12];
#pragma unroll
    for (int j = 0; j < 12; j++) {
        int id = tid + j * 256;
        bl_s[j] = id >> 10;
        bl_n[j] = (id >> 3) & 127;
        bl_u[j] = id & 7;
    }

    auto issue = [&](int i, int st) {
        char* sa = smem + st * STAGE_BYTES;
        const char* asrc = wsrc + (size_t)i * 49152;
        unsigned au = (unsigned)__cvta_generic_to_shared(sa);
#pragma unroll
        for (int j = 0; j < 12; j++) {
            int off = (tid + j * 256) * 16;
            asm volatile("cp.async.cg.shared.global [%0], [%1], 16;"
                         :: "r"(au + off), "l"(asrc + off));
        }
        int t = i >> 5, c32 = i & 31;
        int kh = t / 3, kw = t - kh * 3;
        unsigned bu = au + B_OFF;
#pragma unroll
        for (int j = 0; j < 12; j++) {
            int n = bl_n[j];
            int pr = h0 + (n >> 6) + kh;
            int pc = (n & 63) + kw;
            const float* src = xb + (size_t)(pr * 66 + pc) * 3072 + (bl_s[j] << 10)
                                  + (c32 << 5) + (bl_u[j] << 2);
            unsigned dst = bu + bl_s[j] * 18432 + n * 144 + bl_u[j] * 16;
            asm volatile("cp.async.cg.shared.global [%0], [%1], 16;"
                         :: "r"(dst), "l"(src));
        }
        asm volatile("cp.async.commit_group;");
    };

    issue(0, 0);

    for (int i = 0; i < NITER; i++) {
        const int st = i & 1;
        if (i + 1 < NITER) {
            issue(i + 1, st ^ 1);
            asm volatile("cp.async.wait_group 1;");
        } else {
            asm volatile("cp.async.wait_group 0;");
        }
        __syncthreads();

        const char* sa = smem + st * STAGE_BYTES;
#pragma unroll
        for (int kk8 = 0; kk8 < 4; kk8++) {
            uint32_t bb[3][4][2];
#pragma unroll
            for (int s = 0; s < 3; s++)
#pragma unroll
                for (int nf = 0; nf < 4; nf++) {
                    const char* ba = sa + B_OFF + s * 18432
                        + (wn * 32 + nf * 8 + (lane >> 2)) * 144
                        + (kk8 * 8 + (lane & 3)) * 4;
                    bb[s][nf][0] = *(const uint32_t*)ba;
                    bb[s][nf][1] = *(const uint32_t*)(ba + 16);
                }
            {
                uint4 a[4];
#pragma unroll
                for (int mf = 0; mf < 4; mf++)
                    a[mf] = *(const uint4*)(sa +
                        (((kk8 * 3 + 0) * 8 + (wm * 4 + mf)) * 512) + lane * 16);
#pragma unroll
                for (int mf = 0; mf < 4; mf++)
#pragma unroll
                    for (int nf = 0; nf < 4; nf++) {
                        MMA_TF32(acc[mf][nf], a[mf], bb[0][nf]);
                        MMA_TF32(acc[mf][nf], a[mf], bb[1][nf]);
                        MMA_TF32(acc[mf][nf], a[mf], bb[2][nf]);
                    }
            }
            {
                uint4 a[4];
#pragma unroll
                for (int mf = 0; mf < 4; mf++)
                    a[mf] = *(const uint4*)(sa +
                        (((kk8 * 3 + 1) * 8 + (wm * 4 + mf)) * 512) + lane * 16);
#pragma unroll
                for (int mf = 0; mf < 4; mf++)
#pragma unroll
                    for (int nf = 0; nf < 4; nf++) {
                        MMA_TF32(acc[mf][nf], a[mf], bb[0][nf]);
                        MMA_TF32(acc[mf][nf], a[mf], bb[1][nf]);
                    }
            }
            {
                uint4 a[4];
#pragma unroll
                for (int mf = 0; mf < 4; mf++)
                    a[mf] = *(const uint4*)(sa +
                        (((kk8 * 3 + 2) * 8 + (wm * 4 + mf)) * 512) + lane * 16);
#pragma unroll
                for (int mf = 0; mf < 4; mf++)
#pragma unroll
                    for (int nf = 0; nf < 4; nf++)
                        MMA_TF32(acc[mf][nf], a[mf], bb[0][nf]);
            }
        }
        __syncthreads();

        if ((i & 15) == 15) {
#pragma unroll
            for (int mf = 0; mf < 4; mf++)
#pragma unroll
                for (int nf = 0; nf < 4; nf++)
#pragma unroll
                    for (int r = 0; r < 4; r++) {
                        accR[mf][nf][r] += acc[mf][nf][r];
                        acc[mf][nf][r] = 0.f;
                    }
        }
    }

#pragma unroll
    for (int mf = 0; mf < 4; mf++) {
        int oc0 = mt * 128 + wm * 64 + mf * 16 + (lane >> 2);
        float bias0 = bc[oc0];
        float bias8 = bc[oc0 + 8];
#pragma unroll
        for (int nf = 0; nf < 4; nf++) {
            int nl = wn * 32 + nf * 8 + (lane & 3) * 2;
            int h = h0 + (nl >> 6);
            int w = nl & 63;
            float2 v0, v1;
            v0.x = fmaxf(accR[mf][nf][0] + acc[mf][nf][0] + bias0, 0.f);
            v0.y = fmaxf(accR[mf][nf][1] + acc[mf][nf][1] + bias0, 0.f);
            v1.x = fmaxf(accR[mf][nf][2] + acc[mf][nf][2] + bias8, 0.f);
            v1.y = fmaxf(accR[mf][nf][3] + acc[mf][nf][3] + bias8, 0.f);
            *(float2*)(g_x + (((size_t)(b * OC + oc0) * HH + h) * WWW + w))     = v0;
            *(float2*)(g_x + (((size_t)(b * OC + oc0 + 8) * HH + h) * WWW + w)) = v1;
        }
    }
}

// ============ Kernel 2: heads (validated 64-thread version) ===================
__global__ __launch_bounds__(64) void heads_kernel(
    const float* __restrict__ meta,
    const float* __restrict__ Wcls, const float* __restrict__ bcls,
    const float* __restrict__ Wbb,  const float* __restrict__ bbb)
{
    __shared__ float sw[512 * 20];
    __shared__ float sb[20];

    const int h = blockIdx.x, b = blockIdx.y, tid = threadIdx.x;

    for (int idx = tid; idx < 512 * 20; idx += 64) {
        int c = idx / 20, o = idx - c * 20;
        sw[idx] = (o < 4) ? Wcls[o * 512 + c] : Wbb[(o - 4) * 512 + c];
    }
    if (tid < 20) sb[tid] = (tid < 4) ? bcls[tid] : bbb[tid - 4];
    __syncthreads();

    const int w = tid;
    float acc[20];
#pragma unroll
    for (int o = 0; o < 20; o++) acc[o] = 0.f;

    const float* xp = g_x + ((size_t)(b * OC) * HH + h) * WWW + w;
    for (int c = 0; c < 512; c++) {
        float xv = xp[(size_t)c * HH * WWW];
        const float4* wp = reinterpret_cast<const float4*>(&sw[c * 20]);
        float4 w0 = wp[0], w1 = wp[1], w2 = wp[2], w3 = wp[3], w4 = wp[4];
        acc[0]  = fmaf(xv, w0.x, acc[0]);  acc[1]  = fmaf(xv, w0.y, acc[1]);
        acc[2]  = fmaf(xv, w0.z, acc[2]);  acc[3]  = fmaf(xv, w0.w, acc[3]);
        acc[4]  = fmaf(xv, w1.x, acc[4]);  acc[5]  = fmaf(xv, w1.y, acc[5]);
        acc[6]  = fmaf(xv, w1.z, acc[6]);  acc[7]  = fmaf(xv, w1.w, acc[7]);
        acc[8]  = fmaf(xv, w2.x, acc[8]);  acc[9]  = fmaf(xv, w2.y, acc[9]);
        acc[10] = fmaf(xv, w2.z, acc[10]); acc[11] = fmaf(xv, w2.w, acc[11]);
        acc[12] = fmaf(xv, w3.x, acc[12]); acc[13] = fmaf(xv, w3.y, acc[13]);
        acc[14] = fmaf(xv, w3.z, acc[14]); acc[15] = fmaf(xv, w3.w, acc[15]);
        acc[16] = fmaf(xv, w4.x, acc[16]); acc[17] = fmaf(xv, w4.y, acc[17]);
        acc[18] = fmaf(xv, w4.z, acc[18]); acc[19] = fmaf(xv, w4.w, acc[19]);
    }

    float s[4];
#pragma unroll
    for (int a = 0; a < 4; a++) s[a] = acc[a] + sb[a];
    float prob[4];
#pragma unroll
    for (int a = 0; a < 4; a++) {
        int p = a ^ 2;
        float m  = fmaxf(s[a], s[p]);
        float ea = expf(s[a] - m);
        float eb = expf(s[p] - m);
        prob[a]  = ea / (ea + eb);
    }

    const float im_h = meta[b * 3 + 0];
    const float im_w = meta[b * 3 + 1];
    const float scl  = meta[b * 3 + 2];
    const float minsz = 16.f * scl;

    const int base = b * NA + (h * 64 + w) * 4;
#pragma unroll
    for (int a = 0; a < 4; a++) {
        float wa = (float)(64 << a);
        float cx = w * 16.f + 8.f;
        float cy = h * 16.f + 8.f;
        float d0 = acc[4 + a * 4 + 0] + sb[4 + a * 4 + 0];
        float d1 = acc[4 + a * 4 + 1] + sb[4 + a * 4 + 1];
        float d2 = acc[4 + a * 4 + 2] + sb[4 + a * 4 + 2];
        float d3 = acc[4 + a * 4 + 3] + sb[4 + a * 4 + 3];
        float pcx = d0 * wa + cx, pcy = d1 * wa + cy;
        float pw  = expf(d2) * wa, ph = expf(d3) * wa;
        float x1 = pcx - 0.5f * pw, y1 = pcy - 0.5f * ph;
        float x2 = pcx + 0.5f * pw, y2 = pcy + 0.5f * ph;
        x1 = fminf(fmaxf(x1, 0.f), im_w - 1.f);
        x2 = fminf(fmaxf(x2, 0.f), im_w - 1.f);
        y1 = fminf(fmaxf(y1, 0.f), im_h - 1.f);
        y2 = fminf(fmaxf(y2, 0.f), im_h - 1.f);
        bool keep = (x2 - x1 + 1.f >= minsz) && (y2 - y1 + 1.f >= minsz);
        g_scores[base + a] = keep ? prob[a] : -INFINITY;
        g_boxes[base + a]  = make_float4(x1, y1, x2, y2);
    }
}

// ======== Kernel 3: exact top-6000 + compaction into candidate arrays =========
__global__ __launch_bounds__(1024) void topk_kernel()
{
    const int b   = blockIdx.x;
    const int tid = threadIdx.x;
    const float* scores = g_scores + b * NA;

    __shared__ int wsum[32];
    __shared__ int s_total;
    __shared__ int s_cnt;
    if (tid == 0) s_cnt = 0;

    unsigned key[16];
    const int i0 = tid * 16;
#pragma unroll
    for (int i = 0; i < 16; i++) key[i] = ordkey(scores[i0 + i]);

    const int lane = tid & 31, wid = tid >> 5;

    auto count_ge = [&](unsigned cand) -> int {
        int local = 0;
#pragma unroll
        for (int i = 0; i < 16; i++) local += (key[i] >= cand) ? 1 : 0;
        for (int off = 16; off; off >>= 1)
            local += __shfl_down_sync(0xFFFFFFFFu, local, off);
        if (lane == 0) wsum[wid] = local;
        __syncthreads();
        if (tid == 0) {
            int st = 0;
            for (int k = 0; k < 32; k++) st += wsum[k];
            s_total = st;
        }
        __syncthreads();
        int r = s_total;
        __syncthreads();
        return r;
    };

    unsigned thr = 0;
    for (int bit = 31; bit >= 0; bit--) {
        unsigned cand = thr | (1u << bit);
        if (count_ge(cand) >= PRE_NMS_K) thr = cand;
    }
    const int n_gt = count_ge(thr + 1u);
    const int need = PRE_NMS_K - n_gt;

    int my_eq = 0;
#pragma unroll
    for (int i = 0; i < 16; i++) my_eq += (key[i] == thr) ? 1 : 0;

    int v = my_eq;
    for (int off = 1; off < 32; off <<= 1) {
        int tt = __shfl_up_sync(0xFFFFFFFFu, v, off);
        if (lane >= off) v += tt;
    }
    __syncthreads();
    if (lane == 31) wsum[wid] = v;
    __syncthreads();
    if (wid == 0) {
        int sv = wsum[lane];
        for (int off = 1; off < 32; off <<= 1) {
            int tt = __shfl_up_sync(0xFFFFFFFFu, sv, off);
            if (lane >= off) sv += tt;
        }
        wsum[lane] = sv;
    }
    __syncthreads();
    int rank = v - my_eq + (wid ? wsum[wid - 1] : 0);

    // compact survivors (exactly PRE_NMS_K) into candidate arrays
#pragma unroll
    for (int i = 0; i < 16; i++) {
        bool surv;
        if (key[i] == thr) { surv = (rank < need); rank++; }
        else surv = (key[i] > thr);
        if (surv) {
            int pos = atomicAdd(&s_cnt, 1);
            g_cand_key[b * PRE_NMS_K + pos] =
                ((unsigned long long)key[i] << 32) | (unsigned)(65535 - (i0 + i));
            g_cand_box[b * PRE_NMS_K + pos] = g_boxes[b * NA + i0 + i];
        }
    }
}

// ========= Kernel 4: exact greedy NMS over 6000 candidates in smem ============
__global__ __launch_bounds__(512) void nms_kernel(float* __restrict__ out)
{
    extern __shared__ float4 sbox[];   // NPAD boxes (98304 B, padded)
    const int b   = blockIdx.x;
    const int tid = threadIdx.x;
    const int lane = tid & 31, wid = tid >> 5;

    unsigned long long key[NSLOT];
#pragma unroll
    for (int s = 0; s < NSLOT; s++) {
        int id = tid + s * 512;
        if (id < PRE_NMS_K) {
            key[s]   = g_cand_key[b * PRE_NMS_K + id];
            sbox[id] = g_cand_box[b * PRE_NMS_K + id];
        } else {
            key[s]   = ((unsigned long long)ORD_NEG_INF << 32);
            sbox[id] = make_float4(0.f, 0.f, 0.f, 0.f);   // padded slot
        }
    }

    __shared__ unsigned long long swm[16];
    __shared__ unsigned long long s_best;
    __shared__ float4 s_box;
    __shared__ float  s_area;
    __shared__ float4 s_first;
    __syncthreads();

    for (int it = 0; it < POST_NMS_K; it++) {
        // ---- argmax over keys (max score, lowest orig index on tie) ----
        unsigned long long loc = ((unsigned long long)ORD_NEG_INF << 32);
#pragma unroll
        for (int s = 0; s < NSLOT; s++) loc = (key[s] > loc) ? key[s] : loc;
        for (int off = 16; off; off >>= 1) {
            unsigned long long o = __shfl_down_sync(0xFFFFFFFFu, loc, off);
            loc = (o > loc) ? o : loc;
        }
        if (lane == 0) swm[wid] = loc;
        __syncthreads();
        if (tid < 16) {
            unsigned long long vv = swm[tid];
            for (int off = 8; off; off >>= 1) {
                unsigned long long o = __shfl_down_sync(0x0000FFFFu, vv, off);
                vv = (o > vv) ? o : vv;
            }
            if (tid == 0) s_best = vv;
        }
        __syncthreads();

        const unsigned long long best = s_best;
        const bool exh = ((unsigned)(best >> 32) == ORD_NEG_INF);

        if (!exh) {
            // unique owner publishes box + output row
#pragma unroll
            for (int s = 0; s < NSLOT; s++) {
                if (key[s] == best) {
                    float4 bx = sbox[tid + s * 512];
                    s_box  = bx;
                    s_area = (bx.z - bx.x + 1.f) * (bx.w - bx.y + 1.f);
                    if (it == 0) s_first = bx;
                    float* o = out + (size_t)(b * POST_NMS_K + it) * 5;
                    o[0] = (float)b; o[1] = bx.x; o[2] = bx.y; o[3] = bx.z; o[4] = bx.w;
                }
            }
        }
        __syncthreads();

        if (exh && tid == 0) {
            float4 bx = s_first;    // exhausted pool repeats first selection
            float* o = out + (size_t)(b * POST_NMS_K + it) * 5;
            o[0] = (float)b; o[1] = bx.x; o[2] = bx.y; o[3] = bx.z; o[4] = bx.w;
        }

        const float4 jb = s_box;
        const float  ja = s_area;
#pragma unroll
        for (int s = 0; s < NSLOT; s++) {
            float4 bb = sbox[tid + s * 512];
            float xx1 = fmaxf(jb.x, bb.x);
            float yy1 = fmaxf(jb.y, bb.y);
            float xx2 = fminf(jb.z, bb.z);
            float yy2 = fminf(jb.w, bb.w);
            float iw  = fmaxf(xx2 - xx1 + 1.f, 0.f);
            float ih  = fmaxf(yy2 - yy1 + 1.f, 0.f);
            float inter = iw * ih;
            float area  = (bb.z - bb.x + 1.f) * (bb.w - bb.y + 1.f);
            float iou   = inter / (ja + area - inter);
            if (iou > 0.7f)
                key[s] = ((unsigned long long)ORD_NEG_INF << 32) |
                         (key[s] & 0xFFFFFFFFull);
        }
        __syncthreads();
    }
}

// ================================ launcher ====================================
extern "C" void kernel_launch(void* const* d_in, const int* in_sizes, int n_in,
                              void* d_out, int out_size)
{
    const float* feat = (const float*)d_in[0];
    const float* meta = (const float*)d_in[1];
    // d_in[2] = gt_boxes (unused by the reference output)
    const float* Wc   = (const float*)d_in[3];
    const float* bc   = (const float*)d_in[4];
    const float* Wcls = (const float*)d_in[5];
    const float* bcls = (const float*)d_in[6];
    const float* Wbb  = (const float*)d_in[7];
    const float* bbb  = (const float*)d_in[8];
    float* out = (float*)d_out;

    cudaFuncSetAttribute(conv_mma_kernel,
                         cudaFuncAttributeMaxDynamicSharedMemorySize, CONV_SMEM);
    cudaFuncSetAttribute(nms_kernel,
                         cudaFuncAttributeMaxDynamicSharedMemorySize, NMS_SMEM);

    prep_w_tc<<<(4 * NKK8 * 1024 + 255) / 256, 256>>>(Wc);
    prep_x_tc<<<(NB * 66 * 66 * 1024 + 255) / 256, 256>>>(feat);
    conv_mma_kernel<<<dim3(4, 32, 2), 256, CONV_SMEM>>>(bc);
    heads_kernel<<<dim3(64, 2), 64>>>(meta, Wcls, bcls, Wbb, bbb);
    topk_kernel<<<2, 1024>>>();
    nms_kernel<<<2, 512, NMS_SMEM>>>(out);
}